// round 6
// baseline (speedup 1.0000x reference)
#include <cuda_runtime.h>
#include <cstdint>

// ---------------- problem constants ----------------
#define B_IMG   2
#define N_PROP  2000
#define N_GT    16
#define NPROPS  2016          // N_PROP + N_GT
#define C_FEAT  256
#define HF      128
#define WF      128
#define BPI     512
#define NPOS_MAX 128
#define HID     1024
#define DIN     12544         // C_FEAT * 7 * 7
#define NSAMP   1024          // B_IMG * BPI

// ---------------- device scratch (no allocations allowed) ----------------
__device__ float g_props  [B_IMG * NPROPS * 4];
__device__ int   g_match  [B_IMG * NPROPS];
__device__ int   g_lab    [B_IMG * NPROPS];
__device__ float g_rand   [B_IMG * NPROPS];
__device__ float g_boxes  [NSAMP * 4];
__device__ int   g_labels [NSAMP];
__device__ float g_targets[NSAMP * 6];
__device__ __align__(16) float g_pooled[NSAMP * DIN];   // 51.4 MB
__device__ __align__(16) float g_x1[NSAMP * HID];
__device__ __align__(16) float g_x2[NSAMP * HID];
__device__ float g_logits [NSAMP * 2];
__device__ float g_reg    [NSAMP * 12];

// ---------------- threefry2x32 with key = (0, 42) (jax.random.key(42)) ----------------
__device__ __forceinline__ uint32_t rotl32(uint32_t x, int r) {
    return (x << r) | (x >> (32 - r));
}

__device__ __forceinline__ void threefry_0_42(uint32_t c0, uint32_t c1,
                                              uint32_t& o0, uint32_t& o1) {
    const uint32_t k0 = 0u, k1 = 42u, k2 = 0x1BD11BDAu ^ 0u ^ 42u;
    uint32_t x0 = c0 + k0, x1 = c1 + k1;
#define TFR(r) { x0 += x1; x1 = rotl32(x1, r); x1 ^= x0; }
    TFR(13) TFR(15) TFR(26) TFR(6)   x0 += k1; x1 += k2 + 1u;
    TFR(17) TFR(29) TFR(16) TFR(24)  x0 += k2; x1 += k0 + 2u;
    TFR(13) TFR(15) TFR(26) TFR(6)   x0 += k0; x1 += k1 + 3u;
    TFR(17) TFR(29) TFR(16) TFR(24)  x0 += k1; x1 += k2 + 4u;
    TFR(13) TFR(15) TFR(26) TFR(6)   x0 += k2; x1 += k0 + 5u;
#undef TFR
    o0 = x0; o1 = x1;
}

// ---------------- kernel 1: props + IoU match + label + jax rand ----------------
__global__ void k_prep(const float* __restrict__ proposals,
                       const float* __restrict__ gt_boxes,
                       const int*   __restrict__ gt_labels) {
    int b = blockIdx.y;
    int p = blockIdx.x * blockDim.x + threadIdx.x;

    __shared__ float sg[N_GT * 4];
    __shared__ float sga[N_GT];
    __shared__ int   sgl[N_GT];
    if (threadIdx.x < N_GT) {
        int g = threadIdx.x;
        float gx1 = gt_boxes[(b * N_GT + g) * 4 + 0];
        float gy1 = gt_boxes[(b * N_GT + g) * 4 + 1];
        float gx2 = gt_boxes[(b * N_GT + g) * 4 + 2];
        float gy2 = gt_boxes[(b * N_GT + g) * 4 + 3];
        sg[g * 4 + 0] = gx1; sg[g * 4 + 1] = gy1;
        sg[g * 4 + 2] = gx2; sg[g * 4 + 3] = gy2;
        sga[g] = (gx2 - gx1) * (gy2 - gy1);
        sgl[g] = gt_labels[b * N_GT + g];
    }
    __syncthreads();
    if (p >= NPROPS) return;

    float px1, py1, px2, py2;
    if (p < N_PROP) {
        const float* pp = proposals + (size_t)(b * N_PROP + p) * 4;
        px1 = pp[0]; py1 = pp[1]; px2 = pp[2]; py2 = pp[3];
    } else {
        int g = p - N_PROP;
        px1 = sg[g * 4 + 0]; py1 = sg[g * 4 + 1];
        px2 = sg[g * 4 + 2]; py2 = sg[g * 4 + 3];
    }
    int n = b * NPROPS + p;
    g_props[n * 4 + 0] = px1; g_props[n * 4 + 1] = py1;
    g_props[n * 4 + 2] = px2; g_props[n * 4 + 3] = py2;

    float ap = (px2 - px1) * (py2 - py1);
    float best = -1.0f; int bi = 0;
#pragma unroll
    for (int g = 0; g < N_GT; g++) {
        float ltx = fmaxf(sg[g * 4 + 0], px1);
        float lty = fmaxf(sg[g * 4 + 1], py1);
        float rbx = fminf(sg[g * 4 + 2], px2);
        float rby = fminf(sg[g * 4 + 3], py2);
        float w = fmaxf(rbx - ltx, 0.0f);
        float h = fmaxf(rby - lty, 0.0f);
        float inter = w * h;
        float iou = inter / (sga[g] + ap - inter);
        if (iou > best) { best = iou; bi = g; }   // strict > keeps first max (jax argmax)
    }
    g_match[n] = bi;
    g_lab[n]   = (best < 0.5f) ? 0 : sgl[bi];

    // jax.random.uniform(key(42), (2, 2016)) — PARTITIONABLE threefry
    // (jax_threefry_partitionable defaults to True since JAX 0.4.36):
    //   counter = (hi32(n), lo32(n)) = (0, n);  bits = out0 ^ out1
    uint32_t o0, o1;
    threefry_0_42(0u, (uint32_t)n, o0, o1);
    uint32_t bits = o0 ^ o1;
    g_rand[n] = __uint_as_float((bits >> 9) | 0x3f800000u) - 1.0f;
}

// ---------------- kernel 2: sampling (two bitonic sorts) + gather + encode ----------------
__device__ __forceinline__ unsigned long long pack_key(float f, int i) {
    uint32_t u = __float_as_uint(f);
    u = (u & 0x80000000u) ? ~u : (u | 0x80000000u);   // order-preserving transform
    return ((unsigned long long)u << 32) | (uint32_t)(0x7FF - i);  // lower index wins ties
}

__device__ void bitonic_desc(unsigned long long* keys, int tid) {
    for (int k = 2; k <= 2048; k <<= 1) {
        for (int j = k >> 1; j > 0; j >>= 1) {
            __syncthreads();
            for (int t = tid; t < 2048; t += 1024) {
                int ixj = t ^ j;
                if (ixj > t) {
                    unsigned long long a = keys[t], c = keys[ixj];
                    bool descBlk = ((t & k) == 0);
                    if (descBlk ? (a < c) : (a > c)) { keys[t] = c; keys[ixj] = a; }
                }
            }
        }
    }
    __syncthreads();
}

__global__ __launch_bounds__(1024) void k_sample(const float* __restrict__ gt_ellipses) {
    int b = blockIdx.x;
    int tid = threadIdx.x;
    __shared__ unsigned long long keys[2048];
    __shared__ unsigned char cap[2048];

    // phase 1: rank positives by rand (descending), cap at 128
    for (int i = tid; i < 2048; i += 1024) {
        cap[i] = 0;
        unsigned long long kv = 0ull;
        if (i < NPROPS) {
            float r = g_rand[b * NPROPS + i];
            float s = (g_lab[b * NPROPS + i] > 0) ? r : -1e9f;
            kv = pack_key(s, i);
        }
        keys[i] = kv;
    }
    __syncthreads();
    bitonic_desc(keys, tid);
    if (tid < NPOS_MAX) {
        unsigned long long kv = keys[tid];
        if (kv) {
            int i = 0x7FF - (int)(uint32_t)(kv & 0xFFFFFFFFull);
            if (i >= 0 && i < NPROPS && g_lab[b * NPROPS + i] > 0) cap[i] = 1;
        }
    }
    __syncthreads();

    // phase 2: prio = capped ? rand+2 : (neg ? rand : -1e9); select top-512 set
    for (int i = tid; i < 2048; i += 1024) {
        unsigned long long kv = 0ull;
        if (i < NPROPS) {
            float r = g_rand[b * NPROPS + i];
            float prio = cap[i] ? (r + 2.0f)
                                : ((g_lab[b * NPROPS + i] == 0) ? r : -1e9f);
            kv = pack_key(prio, i);
        }
        keys[i] = kv;
    }
    __syncthreads();
    bitonic_desc(keys, tid);

    if (tid < BPI) {
        int i   = 0x7FF - (int)(uint32_t)(keys[tid] & 0xFFFFFFFFull);
        int n   = b * BPI + tid;
        int src = b * NPROPS + i;
        float x1 = g_props[src * 4 + 0], y1 = g_props[src * 4 + 1];
        float x2 = g_props[src * 4 + 2], y2 = g_props[src * 4 + 3];
        g_boxes[n * 4 + 0] = x1; g_boxes[n * 4 + 1] = y1;
        g_boxes[n * 4 + 2] = x2; g_boxes[n * 4 + 3] = y2;
        int lab = g_lab[src];
        g_labels[n] = lab;
        int m = g_match[src];
        const float* el = gt_ellipses + (size_t)(b * N_GT + m) * 5;
        float ea = el[0], eb = el[1], ex = el[2], ey = el[3], th = el[4];
        float w  = fmaxf(x2 - x1, 1.0f), h = fmaxf(y2 - y1, 1.0f);
        float cx = 0.5f * (x1 + x2),    cy = 0.5f * (y1 + y2);
        g_targets[n * 6 + 0] = (ex - cx) / w;
        g_targets[n * 6 + 1] = (ey - cy) / h;
        g_targets[n * 6 + 2] = logf(fmaxf(2.0f * ea, 0.001f) / w);
        g_targets[n * 6 + 3] = logf(fmaxf(2.0f * eb, 0.001f) / h);
        g_targets[n * 6 + 4] = sinf(2.0f * th);
        g_targets[n * 6 + 5] = cosf(2.0f * th);
    }
}

// ---------------- kernel 3: RoI-align (block per roi) ----------------
__global__ __launch_bounds__(256) void k_roi(const float* __restrict__ features) {
    int n   = blockIdx.x;       // 0..1023
    int b   = n >> 9;
    int tid = threadIdx.x;

    __shared__ int   sy0[14], sx0[14];
    __shared__ float sly[14], slx[14];
    if (tid < 28) {
        float bx1 = g_boxes[n * 4 + 0] * 0.125f;
        float by1 = g_boxes[n * 4 + 1] * 0.125f;
        float bx2 = g_boxes[n * 4 + 2] * 0.125f;
        float by2 = g_boxes[n * 4 + 3] * 0.125f;
        float bw = fmaxf(bx2 - bx1, 1.0f) / 7.0f;
        float bh = fmaxf(by2 - by1, 1.0f) / 7.0f;
        if (tid < 14) {
            float off = ((float)tid + 0.5f) / 2.0f;
            float ys = fminf(fmaxf(by1 + off * bh, 0.0f), 127.0f);
            int y0 = (int)floorf(ys); y0 = min(max(y0, 0), 126);
            sy0[tid] = y0; sly[tid] = ys - (float)y0;
        } else {
            int i = tid - 14;
            float off = ((float)i + 0.5f) / 2.0f;
            float xs = fminf(fmaxf(bx1 + off * bw, 0.0f), 127.0f);
            int x0 = (int)floorf(xs); x0 = min(max(x0, 0), 126);
            sx0[i] = x0; slx[i] = xs - (float)x0;
        }
    }
    __syncthreads();

    const float* fb   = features + (size_t)b * C_FEAT * HF * WF;
    float*       outp = g_pooled + (size_t)n * DIN;

    for (int it = 0; it < 49; it++) {        // 49 * 256 = 12544 exactly
        int e = it * 256 + tid;
        int c = e / 49;
        int r = e - c * 49;
        int py = r / 7, px = r - py * 7;
        const float* fc = fb + (size_t)c * (HF * WF);
        float acc = 0.0f;
#pragma unroll
        for (int sy = 0; sy < 2; sy++) {
            int i = py * 2 + sy;
            int y0 = sy0[i]; float fy = sly[i];
            const float* rowp = fc + y0 * WF;
#pragma unroll
            for (int sx = 0; sx < 2; sx++) {
                int j = px * 2 + sx;
                int x0 = sx0[j]; float fx = slx[j];
                float v00 = __ldg(rowp + x0);
                float v01 = __ldg(rowp + x0 + 1);
                float v10 = __ldg(rowp + WF + x0);
                float v11 = __ldg(rowp + WF + x0 + 1);
                float top = v00 + (v01 - v00) * fx;
                float bot = v10 + (v11 - v10) * fx;
                acc += top + (bot - top) * fy;
            }
        }
        outp[e] = acc * 0.25f;
    }
}

// ---------------- kernel 4: fp32 tiled GEMM + bias + ReLU ----------------
// C[M,N] = relu(A[M,K] @ B[K,N] + bias[N]); 64x64 tile, 256 threads, 4x4 micro-tile
__global__ __launch_bounds__(256) void k_gemm_relu(const float* __restrict__ A,
                                                   const float* __restrict__ B,
                                                   const float* __restrict__ bias,
                                                   float* __restrict__ C,
                                                   int M, int N, int K) {
    __shared__ float As[16][64];   // [k][m] (transposed on store)
    __shared__ float Bs[16][64];   // [k][n]
    int tid = threadIdx.x;
    int m0 = blockIdx.y * 64, n0 = blockIdx.x * 64;
    int ty = tid >> 4, tx = tid & 15;
    int am = tid >> 2,  ak = (tid & 3) * 4;
    int bk = tid >> 4,  bn = (tid & 15) * 4;
    const float* Ap = A + (size_t)(m0 + am) * K + ak;

    float acc[4][4];
#pragma unroll
    for (int i = 0; i < 4; i++)
#pragma unroll
        for (int j = 0; j < 4; j++) acc[i][j] = 0.0f;

    for (int k0 = 0; k0 < K; k0 += 16) {
        float4 av = *(const float4*)(Ap + k0);
        float4 bv = *(const float4*)(B + (size_t)(k0 + bk) * N + n0 + bn);
        As[ak + 0][am] = av.x; As[ak + 1][am] = av.y;
        As[ak + 2][am] = av.z; As[ak + 3][am] = av.w;
        *(float4*)(&Bs[bk][bn]) = bv;
        __syncthreads();
#pragma unroll
        for (int kk = 0; kk < 16; kk++) {
            float4 a  = *(const float4*)(&As[kk][ty * 4]);
            float4 bq = *(const float4*)(&Bs[kk][tx * 4]);
            float ar[4] = {a.x, a.y, a.z, a.w};
            float br_[4] = {bq.x, bq.y, bq.z, bq.w};
#pragma unroll
            for (int i = 0; i < 4; i++)
#pragma unroll
                for (int j = 0; j < 4; j++)
                    acc[i][j] = fmaf(ar[i], br_[j], acc[i][j]);
        }
        __syncthreads();
    }

#pragma unroll
    for (int j = 0; j < 4; j++) {
        float bsv = bias[n0 + tx * 4 + j];
#pragma unroll
        for (int i = 0; i < 4; i++) {
            float v = acc[i][j] + bsv;
            C[(size_t)(m0 + ty * 4 + i) * N + n0 + tx * 4 + j] = fmaxf(v, 0.0f);
        }
    }
}

// ---------------- kernel 5: classification + regression heads ----------------
__global__ __launch_bounds__(128) void k_heads(const float* __restrict__ wc,
                                               const float* __restrict__ bc,
                                               const float* __restrict__ wr,
                                               const float* __restrict__ br) {
    int n = blockIdx.x, tid = threadIdx.x;
    float acc[14];
#pragma unroll
    for (int o = 0; o < 14; o++) acc[o] = 0.0f;
    const float* xr = g_x2 + (size_t)n * HID;
    for (int k = tid; k < HID; k += 128) {
        float xv = xr[k];
        acc[0] = fmaf(xv, wc[k * 2 + 0], acc[0]);
        acc[1] = fmaf(xv, wc[k * 2 + 1], acc[1]);
#pragma unroll
        for (int j = 0; j < 12; j++)
            acc[2 + j] = fmaf(xv, wr[k * 12 + j], acc[2 + j]);
    }
    __shared__ float sh[128];
    for (int o = 0; o < 14; o++) {
        sh[tid] = acc[o]; __syncthreads();
        for (int s = 64; s > 0; s >>= 1) {
            if (tid < s) sh[tid] += sh[tid + s];
            __syncthreads();
        }
        if (tid == 0) {
            float v = sh[0] + (o < 2 ? bc[o] : br[o - 2]);
            if (o < 2) g_logits[n * 2 + o] = v;
            else       g_reg[n * 12 + (o - 2)] = v;
        }
        __syncthreads();
    }
}

// ---------------- kernel 6: losses ----------------
__global__ __launch_bounds__(1024) void k_loss(float* __restrict__ out) {
    int tid = threadIdx.x;
    const float BETA = 1.0f / 9.0f;
    float l0 = g_logits[tid * 2 + 0], l1 = g_logits[tid * 2 + 1];
    int lab = g_labels[tid];
    float mx  = fmaxf(l0, l1);
    float lse = mx + logf(expf(l0 - mx) + expf(l1 - mx));
    float ce  = lse - g_logits[tid * 2 + lab];
    float rl = 0.0f;
    if (lab > 0) {
        const float* pr = g_reg + tid * 12 + lab * 6;
        const float* tg = g_targets + tid * 6;
#pragma unroll
        for (int j = 0; j < 6; j++) {
            float d = fabsf(pr[j] - tg[j]);
            rl += (d < BETA) ? (0.5f * d * d / BETA) : (d - 0.5f * BETA);
        }
    }
    __shared__ float sce[1024];
    __shared__ float srl[1024];
    sce[tid] = ce; srl[tid] = rl;
    __syncthreads();
    for (int s = 512; s > 0; s >>= 1) {
        if (tid < s) { sce[tid] += sce[tid + s]; srl[tid] += srl[tid + s]; }
        __syncthreads();
    }
    if (tid == 0) {
        out[0] = sce[0] / (float)NSAMP;
        out[1] = srl[0] / (float)NSAMP;
    }
}

// ---------------- launch ----------------
extern "C" void kernel_launch(void* const* d_in, const int* in_sizes, int n_in,
                              void* d_out, int out_size) {
    const float* features    = (const float*)d_in[0];
    const float* proposals   = (const float*)d_in[1];
    const float* gt_boxes    = (const float*)d_in[2];
    const int*   gt_labels   = (const int*)  d_in[3];
    const float* gt_ellipses = (const float*)d_in[4];
    const float* w1 = (const float*)d_in[5];
    const float* b1 = (const float*)d_in[6];
    const float* w2 = (const float*)d_in[7];
    const float* b2 = (const float*)d_in[8];
    const float* wc = (const float*)d_in[9];
    const float* bc = (const float*)d_in[10];
    const float* wr = (const float*)d_in[11];
    const float* br = (const float*)d_in[12];
    float* out = (float*)d_out;

    float* px1; float* px2; float* ppool;
    cudaGetSymbolAddress((void**)&ppool, g_pooled);
    cudaGetSymbolAddress((void**)&px1,   g_x1);
    cudaGetSymbolAddress((void**)&px2,   g_x2);

    k_prep<<<dim3(8, 2), 256>>>(proposals, gt_boxes, gt_labels);
    k_sample<<<2, 1024>>>(gt_ellipses);
    k_roi<<<NSAMP, 256>>>(features);
    k_gemm_relu<<<dim3(16, 16), 256>>>(ppool, w1, b1, px1, NSAMP, HID, DIN);
    k_gemm_relu<<<dim3(16, 16), 256>>>(px1,  w2, b2, px2, NSAMP, HID, HID);
    k_heads<<<NSAMP, 128>>>(wc, bc, wr, br);
    k_loss<<<1, 1024>>>(out);
}

// round 8
// speedup vs baseline: 1.4977x; 1.4977x over previous
#include <cuda_runtime.h>
#include <cuda_bf16.h>
#include <cstdint>

#define B_IMG   2
#define N_PROP  2000
#define N_GT    16
#define NPROPS  2016
#define C_FEAT  256
#define HF      128
#define WF      128
#define BPI     512
#define NPOS_MAX 128
#define HID     1024
#define DIN     12544
#define NSAMP   1024

// ---------------- device scratch ----------------
__device__ float g_props  [B_IMG * NPROPS * 4];
__device__ int   g_match  [B_IMG * NPROPS];
__device__ int   g_lab    [B_IMG * NPROPS];
__device__ float g_rand   [B_IMG * NPROPS];
__device__ float g_boxes  [NSAMP * 4];
__device__ int   g_labels [NSAMP];
__device__ float g_targets[NSAMP * 6];
__device__ __align__(16) __nv_bfloat16 g_ahi [NSAMP * DIN];
__device__ __align__(16) __nv_bfloat16 g_alo [NSAMP * DIN];
__device__ __align__(16) __nv_bfloat16 g_w1th[HID * DIN];
__device__ __align__(16) __nv_bfloat16 g_w1tl[HID * DIN];
__device__ __align__(16) __nv_bfloat16 g_x1h [NSAMP * HID];
__device__ __align__(16) __nv_bfloat16 g_x1l [NSAMP * HID];
__device__ __align__(16) __nv_bfloat16 g_w2th[HID * HID];
__device__ __align__(16) __nv_bfloat16 g_w2tl[HID * HID];
__device__ __align__(16) float g_x2[NSAMP * HID];
__device__ float g_logits [NSAMP * 2];
__device__ float g_reg    [NSAMP * 12];

// ---------------- helpers ----------------
__device__ __forceinline__ uint32_t smem_u32(const void* p) {
    uint32_t a;
    asm("{ .reg .u64 t; cvta.to.shared.u64 t, %1; cvt.u32.u64 %0, t; }" : "=r"(a) : "l"(p));
    return a;
}
__device__ __forceinline__ void cp16(uint32_t saddr, const void* g) {
    asm volatile("cp.async.cg.shared.global [%0], [%1], 16;" :: "r"(saddr), "l"(g));
}
__device__ __forceinline__ void ldsm4(uint32_t* r, uint32_t a) {
    asm volatile("ldmatrix.sync.aligned.m8n8.x4.shared.b16 {%0,%1,%2,%3}, [%4];"
                 : "=r"(r[0]), "=r"(r[1]), "=r"(r[2]), "=r"(r[3]) : "r"(a));
}
__device__ __forceinline__ void ldsm2(uint32_t* r, uint32_t a) {
    asm volatile("ldmatrix.sync.aligned.m8n8.x2.shared.b16 {%0,%1}, [%2];"
                 : "=r"(r[0]), "=r"(r[1]) : "r"(a));
}
__device__ __forceinline__ void mma_bf16(float* d, const uint32_t* a, const uint32_t* b) {
    asm volatile("mma.sync.aligned.m16n8k16.row.col.f32.bf16.bf16.f32 "
                 "{%0,%1,%2,%3},{%4,%5,%6,%7},{%8,%9},{%0,%1,%2,%3};"
                 : "+f"(d[0]), "+f"(d[1]), "+f"(d[2]), "+f"(d[3])
                 : "r"(a[0]), "r"(a[1]), "r"(a[2]), "r"(a[3]), "r"(b[0]), "r"(b[1]));
}
__device__ __forceinline__ void bf_split(float f, __nv_bfloat16& h, __nv_bfloat16& l) {
    h = __float2bfloat16_rn(f);
    l = __float2bfloat16_rn(f - __bfloat162float(h));
}

// ---------------- threefry2x32, key=(0,42), partitionable ----------------
__device__ __forceinline__ uint32_t rotl32(uint32_t x, int r) { return (x << r) | (x >> (32 - r)); }
__device__ __forceinline__ void threefry_0_42(uint32_t c0, uint32_t c1, uint32_t& o0, uint32_t& o1) {
    const uint32_t k0 = 0u, k1 = 42u, k2 = 0x1BD11BDAu ^ 42u;
    uint32_t x0 = c0 + k0, x1 = c1 + k1;
#define TFR(r) { x0 += x1; x1 = rotl32(x1, r); x1 ^= x0; }
    TFR(13) TFR(15) TFR(26) TFR(6)   x0 += k1; x1 += k2 + 1u;
    TFR(17) TFR(29) TFR(16) TFR(24)  x0 += k2; x1 += k0 + 2u;
    TFR(13) TFR(15) TFR(26) TFR(6)   x0 += k0; x1 += k1 + 3u;
    TFR(17) TFR(29) TFR(16) TFR(24)  x0 += k1; x1 += k2 + 4u;
    TFR(13) TFR(15) TFR(26) TFR(6)   x0 += k2; x1 += k0 + 5u;
#undef TFR
    o0 = x0; o1 = x1;
}

// ---------------- kernel 1: props + IoU + label + rand ----------------
__global__ void k_prep(const float* __restrict__ proposals,
                       const float* __restrict__ gt_boxes,
                       const int*   __restrict__ gt_labels) {
    int b = blockIdx.y;
    int p = blockIdx.x * blockDim.x + threadIdx.x;
    __shared__ float sg[N_GT * 4];
    __shared__ float sga[N_GT];
    __shared__ int   sgl[N_GT];
    if (threadIdx.x < N_GT) {
        int g = threadIdx.x;
        float gx1 = gt_boxes[(b * N_GT + g) * 4 + 0];
        float gy1 = gt_boxes[(b * N_GT + g) * 4 + 1];
        float gx2 = gt_boxes[(b * N_GT + g) * 4 + 2];
        float gy2 = gt_boxes[(b * N_GT + g) * 4 + 3];
        sg[g * 4 + 0] = gx1; sg[g * 4 + 1] = gy1;
        sg[g * 4 + 2] = gx2; sg[g * 4 + 3] = gy2;
        sga[g] = (gx2 - gx1) * (gy2 - gy1);
        sgl[g] = gt_labels[b * N_GT + g];
    }
    __syncthreads();
    if (p >= NPROPS) return;
    float px1, py1, px2, py2;
    if (p < N_PROP) {
        const float* pp = proposals + (size_t)(b * N_PROP + p) * 4;
        px1 = pp[0]; py1 = pp[1]; px2 = pp[2]; py2 = pp[3];
    } else {
        int g = p - N_PROP;
        px1 = sg[g * 4 + 0]; py1 = sg[g * 4 + 1];
        px2 = sg[g * 4 + 2]; py2 = sg[g * 4 + 3];
    }
    int n = b * NPROPS + p;
    g_props[n * 4 + 0] = px1; g_props[n * 4 + 1] = py1;
    g_props[n * 4 + 2] = px2; g_props[n * 4 + 3] = py2;
    float ap = (px2 - px1) * (py2 - py1);
    float best = -1.0f; int bi = 0;
#pragma unroll
    for (int g = 0; g < N_GT; g++) {
        float ltx = fmaxf(sg[g * 4 + 0], px1);
        float lty = fmaxf(sg[g * 4 + 1], py1);
        float rbx = fminf(sg[g * 4 + 2], px2);
        float rby = fminf(sg[g * 4 + 3], py2);
        float w = fmaxf(rbx - ltx, 0.0f);
        float h = fmaxf(rby - lty, 0.0f);
        float inter = w * h;
        float iou = inter / (sga[g] + ap - inter);
        if (iou > best) { best = iou; bi = g; }
    }
    g_match[n] = bi;
    g_lab[n]   = (best < 0.5f) ? 0 : sgl[bi];
    uint32_t o0, o1;
    threefry_0_42(0u, (uint32_t)n, o0, o1);
    uint32_t bits = o0 ^ o1;
    g_rand[n] = __uint_as_float((bits >> 9) | 0x3f800000u) - 1.0f;
}

// ---------------- kernel 2: sampling ----------------
__device__ __forceinline__ unsigned long long pack_key(float f, int i) {
    uint32_t u = __float_as_uint(f);
    u = (u & 0x80000000u) ? ~u : (u | 0x80000000u);
    return ((unsigned long long)u << 32) | (uint32_t)(0x7FF - i);
}
__device__ void bitonic_desc(unsigned long long* keys, int tid) {
    for (int k = 2; k <= 2048; k <<= 1)
        for (int j = k >> 1; j > 0; j >>= 1) {
            __syncthreads();
            for (int t = tid; t < 2048; t += 1024) {
                int ixj = t ^ j;
                if (ixj > t) {
                    unsigned long long a = keys[t], c = keys[ixj];
                    bool descBlk = ((t & k) == 0);
                    if (descBlk ? (a < c) : (a > c)) { keys[t] = c; keys[ixj] = a; }
                }
            }
        }
    __syncthreads();
}
__global__ __launch_bounds__(1024) void k_sample(const float* __restrict__ gt_ellipses) {
    int b = blockIdx.x, tid = threadIdx.x;
    __shared__ unsigned long long keys[2048];
    __shared__ unsigned char cap[2048];
    for (int i = tid; i < 2048; i += 1024) {
        cap[i] = 0;
        unsigned long long kv = 0ull;
        if (i < NPROPS) {
            float r = g_rand[b * NPROPS + i];
            float s = (g_lab[b * NPROPS + i] > 0) ? r : -1e9f;
            kv = pack_key(s, i);
        }
        keys[i] = kv;
    }
    __syncthreads();
    bitonic_desc(keys, tid);
    if (tid < NPOS_MAX) {
        unsigned long long kv = keys[tid];
        if (kv) {
            int i = 0x7FF - (int)(uint32_t)(kv & 0xFFFFFFFFull);
            if (i >= 0 && i < NPROPS && g_lab[b * NPROPS + i] > 0) cap[i] = 1;
        }
    }
    __syncthreads();
    for (int i = tid; i < 2048; i += 1024) {
        unsigned long long kv = 0ull;
        if (i < NPROPS) {
            float r = g_rand[b * NPROPS + i];
            float prio = cap[i] ? (r + 2.0f)
                                : ((g_lab[b * NPROPS + i] == 0) ? r : -1e9f);
            kv = pack_key(prio, i);
        }
        keys[i] = kv;
    }
    __syncthreads();
    bitonic_desc(keys, tid);
    if (tid < BPI) {
        int i   = 0x7FF - (int)(uint32_t)(keys[tid] & 0xFFFFFFFFull);
        int n   = b * BPI + tid;
        int src = b * NPROPS + i;
        float x1 = g_props[src * 4 + 0], y1 = g_props[src * 4 + 1];
        float x2 = g_props[src * 4 + 2], y2 = g_props[src * 4 + 3];
        g_boxes[n * 4 + 0] = x1; g_boxes[n * 4 + 1] = y1;
        g_boxes[n * 4 + 2] = x2; g_boxes[n * 4 + 3] = y2;
        int lab = g_lab[src];
        g_labels[n] = lab;
        int m = g_match[src];
        const float* el = gt_ellipses + (size_t)(b * N_GT + m) * 5;
        float ea = el[0], eb = el[1], ex = el[2], ey = el[3], th = el[4];
        float w  = fmaxf(x2 - x1, 1.0f), h = fmaxf(y2 - y1, 1.0f);
        float cx = 0.5f * (x1 + x2),    cy = 0.5f * (y1 + y2);
        g_targets[n * 6 + 0] = (ex - cx) / w;
        g_targets[n * 6 + 1] = (ey - cy) / h;
        g_targets[n * 6 + 2] = logf(fmaxf(2.0f * ea, 0.001f) / w);
        g_targets[n * 6 + 3] = logf(fmaxf(2.0f * eb, 0.001f) / h);
        g_targets[n * 6 + 4] = sinf(2.0f * th);
        g_targets[n * 6 + 5] = cosf(2.0f * th);
    }
}

// ---------------- kernel 3: RoI-align -> split bf16 ----------------
__global__ __launch_bounds__(256) void k_roi(const float* __restrict__ features) {
    int n   = blockIdx.x;
    int b   = n >> 9;
    int tid = threadIdx.x;
    __shared__ int   sy0[14], sx0[14];
    __shared__ float sly[14], slx[14];
    if (tid < 28) {
        float bx1 = g_boxes[n * 4 + 0] * 0.125f;
        float by1 = g_boxes[n * 4 + 1] * 0.125f;
        float bx2 = g_boxes[n * 4 + 2] * 0.125f;
        float by2 = g_boxes[n * 4 + 3] * 0.125f;
        float bw = fmaxf(bx2 - bx1, 1.0f) / 7.0f;
        float bh = fmaxf(by2 - by1, 1.0f) / 7.0f;
        if (tid < 14) {
            float off = ((float)tid + 0.5f) / 2.0f;
            float ys = fminf(fmaxf(by1 + off * bh, 0.0f), 127.0f);
            int y0 = (int)floorf(ys); y0 = min(max(y0, 0), 126);
            sy0[tid] = y0; sly[tid] = ys - (float)y0;
        } else {
            int i = tid - 14;
            float off = ((float)i + 0.5f) / 2.0f;
            float xs = fminf(fmaxf(bx1 + off * bw, 0.0f), 127.0f);
            int x0 = (int)floorf(xs); x0 = min(max(x0, 0), 126);
            sx0[i] = x0; slx[i] = xs - (float)x0;
        }
    }
    __syncthreads();
    const float* fb = features + (size_t)b * C_FEAT * HF * WF;
    for (int it = 0; it < 49; it++) {
        int e = it * 256 + tid;
        int c = e / 49;
        int r = e - c * 49;
        int py = r / 7, px = r - py * 7;
        const float* fc = fb + (size_t)c * (HF * WF);
        float acc = 0.0f;
#pragma unroll
        for (int sy = 0; sy < 2; sy++) {
            int i = py * 2 + sy;
            int y0 = sy0[i]; float fy = sly[i];
            const float* rowp = fc + y0 * WF;
#pragma unroll
            for (int sx = 0; sx < 2; sx++) {
                int j = px * 2 + sx;
                int x0 = sx0[j]; float fx = slx[j];
                float v00 = __ldg(rowp + x0);
                float v01 = __ldg(rowp + x0 + 1);
                float v10 = __ldg(rowp + WF + x0);
                float v11 = __ldg(rowp + WF + x0 + 1);
                float top = v00 + (v01 - v00) * fx;
                float bot = v10 + (v11 - v10) * fx;
                acc += top + (bot - top) * fy;
            }
        }
        float v = acc * 0.25f;
        __nv_bfloat16 h, l; bf_split(v, h, l);
        g_ahi[(size_t)n * DIN + e] = h;
        g_alo[(size_t)n * DIN + e] = l;
    }
}

// ---------------- transpose + split weights: out[n][k] = split(in[k][n]) ----------------
__global__ void k_splitT(const float* __restrict__ in,
                         __nv_bfloat16* __restrict__ oh,
                         __nv_bfloat16* __restrict__ ol, int K) {
    __shared__ float t[32][33];
    int nb = blockIdx.x * 32, kb = blockIdx.y * 32;
    int tx = threadIdx.x, ty = threadIdx.y;
#pragma unroll
    for (int r = 0; r < 4; r++)
        t[ty + r * 8][tx] = in[(size_t)(kb + ty + r * 8) * HID + nb + tx];
    __syncthreads();
#pragma unroll
    for (int r = 0; r < 4; r++) {
        int n = nb + ty + r * 8;
        float f = t[tx][ty + r * 8];
        __nv_bfloat16 h, l; bf_split(f, h, l);
        oh[(size_t)n * K + kb + tx] = h;
        ol[(size_t)n * K + kb + tx] = l;
    }
}

// ---------------- HMMA split-bf16 GEMM + bias + ReLU ----------------
// C[1024,1024] = relu(A @ B^T + bias); A[M][K], B[N][K] hi/lo bf16.
// CTA 128x128, 8 warps (2x4), warp tile 64x32, BK=32, 2-stage cp.async.
#define ROWPAD 40                    // bf16 per smem row (80 B, conflict-free ldmatrix)
#define TILE_B (128 * ROWPAD * 2)    // 10240 B per tile
#define STAGE_B (4 * TILE_B)         // Ah, Al, Bh, Bl
__global__ __launch_bounds__(256, 1) void k_gemm_mma(
    const __nv_bfloat16* __restrict__ Ah, const __nv_bfloat16* __restrict__ Al,
    const __nv_bfloat16* __restrict__ Bh, const __nv_bfloat16* __restrict__ Bl,
    const float* __restrict__ bias,
    float* __restrict__ Cf, __nv_bfloat16* __restrict__ Ch, __nv_bfloat16* __restrict__ Cl,
    int K)
{
    extern __shared__ char sm[];
    uint32_t sbase = smem_u32(sm);
    int tid = threadIdx.x, wid = tid >> 5, lane = tid & 31;
    int wm = wid >> 2, wn = wid & 3;              // 2 x 4 warp grid
    int m0 = blockIdx.y << 7, n0 = blockIdx.x << 7;

    float acc[4][4][4];
#pragma unroll
    for (int i = 0; i < 4; i++)
#pragma unroll
        for (int j = 0; j < 4; j++)
#pragma unroll
            for (int q = 0; q < 4; q++) acc[i][j][q] = 0.0f;

    int nsteps = K >> 5;

    // stage loader: 512 16B-chunks per tile, 2 per thread per tile
#define LOAD_STAGE(st, k0)                                                  \
    {                                                                       \
        uint32_t sb = sbase + (uint32_t)(st) * STAGE_B;                     \
        _Pragma("unroll")                                                   \
        for (int i = 0; i < 2; i++) {                                       \
            int c   = tid + (i << 8);                                       \
            int row = c >> 2, cc = c & 3;                                   \
            uint32_t so = (uint32_t)(row * (ROWPAD * 2) + cc * 16);         \
            size_t goA = (size_t)(m0 + row) * K + (k0) + cc * 8;            \
            size_t goB = (size_t)(n0 + row) * K + (k0) + cc * 8;            \
            cp16(sb + so,              Ah + goA);                           \
            cp16(sb + TILE_B + so,     Al + goA);                           \
            cp16(sb + 2 * TILE_B + so, Bh + goB);                           \
            cp16(sb + 3 * TILE_B + so, Bl + goB);                           \
        }                                                                   \
        asm volatile("cp.async.commit_group;" ::: "memory");                \
    }

    LOAD_STAGE(0, 0)

    for (int s = 0; s < nsteps; s++) {
        if (s + 1 < nsteps) {
            LOAD_STAGE((s + 1) & 1, (s + 1) << 5)
            asm volatile("cp.async.wait_group 1;" ::: "memory");
        } else {
            asm volatile("cp.async.wait_group 0;" ::: "memory");
        }
        __syncthreads();

        uint32_t sb = sbase + (uint32_t)(s & 1) * STAGE_B;
#pragma unroll
        for (int kc = 0; kc < 2; kc++) {
            uint32_t ah[4][4], al[4][4], bh[4][2], bl[4][2];
            int arow = wm * 64 + (lane & 7) + ((lane >> 3) & 1) * 8;
            int acol = kc * 16 + ((lane >> 4) & 1) * 8;
#pragma unroll
            for (int mi = 0; mi < 4; mi++) {
                uint32_t ad = sb + (uint32_t)((arow + mi * 16) * (ROWPAD * 2) + acol * 2);
                ldsm4(ah[mi], ad);
                ldsm4(al[mi], ad + TILE_B);
            }
            int brow = wn * 32 + (lane & 7);
            int bcol = kc * 16 + ((lane >> 3) & 1) * 8;
#pragma unroll
            for (int ni = 0; ni < 4; ni++) {
                uint32_t bd = sb + 2 * TILE_B + (uint32_t)((brow + ni * 8) * (ROWPAD * 2) + bcol * 2);
                ldsm2(bh[ni], bd);
                ldsm2(bl[ni], bd + TILE_B);
            }
#pragma unroll
            for (int mi = 0; mi < 4; mi++)
#pragma unroll
                for (int ni = 0; ni < 4; ni++) {
                    mma_bf16(acc[mi][ni], ah[mi], bh[ni]);
                    mma_bf16(acc[mi][ni], al[mi], bh[ni]);
                    mma_bf16(acc[mi][ni], ah[mi], bl[ni]);
                }
        }
        __syncthreads();
    }

    // epilogue: c0,c1 -> row r, cols 2c,2c+1 ; c2,c3 -> row r+8
    int r = lane >> 2, cp = (lane & 3) * 2;
#pragma unroll
    for (int mi = 0; mi < 4; mi++) {
        int mA = m0 + wm * 64 + mi * 16 + r;
        int mB = mA + 8;
#pragma unroll
        for (int ni = 0; ni < 4; ni++) {
            int n = n0 + wn * 32 + ni * 8 + cp;
            float b0v = __ldg(bias + n), b1v = __ldg(bias + n + 1);
            float* a = acc[mi][ni];
            float v00 = fmaxf(a[0] + b0v, 0.f), v01 = fmaxf(a[1] + b1v, 0.f);
            float v10 = fmaxf(a[2] + b0v, 0.f), v11 = fmaxf(a[3] + b1v, 0.f);
            if (Cf) {
                *(float2*)(Cf + (size_t)mA * 1024 + n) = make_float2(v00, v01);
                *(float2*)(Cf + (size_t)mB * 1024 + n) = make_float2(v10, v11);
            } else {
                __nv_bfloat16 h0, l0, h1, l1;
                bf_split(v00, h0, l0); bf_split(v01, h1, l1);
                *(ushort2*)(Ch + (size_t)mA * 1024 + n) =
                    make_ushort2(__bfloat16_as_ushort(h0), __bfloat16_as_ushort(h1));
                *(ushort2*)(Cl + (size_t)mA * 1024 + n) =
                    make_ushort2(__bfloat16_as_ushort(l0), __bfloat16_as_ushort(l1));
                bf_split(v10, h0, l0); bf_split(v11, h1, l1);
                *(ushort2*)(Ch + (size_t)mB * 1024 + n) =
                    make_ushort2(__bfloat16_as_ushort(h0), __bfloat16_as_ushort(h1));
                *(ushort2*)(Cl + (size_t)mB * 1024 + n) =
                    make_ushort2(__bfloat16_as_ushort(l0), __bfloat16_as_ushort(l1));
            }
        }
    }
}

// ---------------- heads ----------------
__global__ __launch_bounds__(128) void k_heads(const float* __restrict__ wc,
                                               const float* __restrict__ bc,
                                               const float* __restrict__ wr,
                                               const float* __restrict__ br) {
    int n = blockIdx.x, tid = threadIdx.x;
    float acc[14];
#pragma unroll
    for (int o = 0; o < 14; o++) acc[o] = 0.0f;
    const float* xr = g_x2 + (size_t)n * HID;
    for (int k = tid; k < HID; k += 128) {
        float xv = xr[k];
        acc[0] = fmaf(xv, wc[k * 2 + 0], acc[0]);
        acc[1] = fmaf(xv, wc[k * 2 + 1], acc[1]);
#pragma unroll
        for (int j = 0; j < 12; j++)
            acc[2 + j] = fmaf(xv, wr[k * 12 + j], acc[2 + j]);
    }
    __shared__ float sh[128];
    for (int o = 0; o < 14; o++) {
        sh[tid] = acc[o]; __syncthreads();
        for (int s = 64; s > 0; s >>= 1) {
            if (tid < s) sh[tid] += sh[tid + s];
            __syncthreads();
        }
        if (tid == 0) {
            float v = sh[0] + (o < 2 ? bc[o] : br[o - 2]);
            if (o < 2) g_logits[n * 2 + o] = v;
            else       g_reg[n * 12 + (o - 2)] = v;
        }
        __syncthreads();
    }
}

// ---------------- losses ----------------
__global__ __launch_bounds__(1024) void k_loss(float* __restrict__ out) {
    int tid = threadIdx.x;
    const float BETA = 1.0f / 9.0f;
    float l0 = g_logits[tid * 2 + 0], l1 = g_logits[tid * 2 + 1];
    int lab = g_labels[tid];
    float mx  = fmaxf(l0, l1);
    float lse = mx + logf(expf(l0 - mx) + expf(l1 - mx));
    float ce  = lse - g_logits[tid * 2 + lab];
    float rl = 0.0f;
    if (lab > 0) {
        const float* pr = g_reg + tid * 12 + lab * 6;
        const float* tg = g_targets + tid * 6;
#pragma unroll
        for (int j = 0; j < 6; j++) {
            float d = fabsf(pr[j] - tg[j]);
            rl += (d < BETA) ? (0.5f * d * d / BETA) : (d - 0.5f * BETA);
        }
    }
    __shared__ float sce[1024];
    __shared__ float srl[1024];
    sce[tid] = ce; srl[tid] = rl;
    __syncthreads();
    for (int s = 512; s > 0; s >>= 1) {
        if (tid < s) { sce[tid] += sce[tid + s]; srl[tid] += srl[tid + s]; }
        __syncthreads();
    }
    if (tid == 0) {
        out[0] = sce[0] / (float)NSAMP;
        out[1] = srl[0] / (float)NSAMP;
    }
}

// ---------------- launch ----------------
extern "C" void kernel_launch(void* const* d_in, const int* in_sizes, int n_in,
                              void* d_out, int out_size) {
    const float* features    = (const float*)d_in[0];
    const float* proposals   = (const float*)d_in[1];
    const float* gt_boxes    = (const float*)d_in[2];
    const int*   gt_labels   = (const int*)  d_in[3];
    const float* gt_ellipses = (const float*)d_in[4];
    const float* w1 = (const float*)d_in[5];
    const float* b1 = (const float*)d_in[6];
    const float* w2 = (const float*)d_in[7];
    const float* b2 = (const float*)d_in[8];
    const float* wc = (const float*)d_in[9];
    const float* bc = (const float*)d_in[10];
    const float* wr = (const float*)d_in[11];
    const float* br = (const float*)d_in[12];
    float* out = (float*)d_out;

    __nv_bfloat16 *pah, *pal, *pw1h, *pw1l, *px1h, *px1l, *pw2h, *pw2l;
    float *px2;
    cudaGetSymbolAddress((void**)&pah,  g_ahi);
    cudaGetSymbolAddress((void**)&pal,  g_alo);
    cudaGetSymbolAddress((void**)&pw1h, g_w1th);
    cudaGetSymbolAddress((void**)&pw1l, g_w1tl);
    cudaGetSymbolAddress((void**)&px1h, g_x1h);
    cudaGetSymbolAddress((void**)&px1l, g_x1l);
    cudaGetSymbolAddress((void**)&pw2h, g_w2th);
    cudaGetSymbolAddress((void**)&pw2l, g_w2tl);
    cudaGetSymbolAddress((void**)&px2,  g_x2);

    const int dyn_bytes = 2 * STAGE_B;   // 81920
    cudaFuncSetAttribute(k_gemm_mma, cudaFuncAttributeMaxDynamicSharedMemorySize, dyn_bytes);

    k_prep<<<dim3(8, 2), 256>>>(proposals, gt_boxes, gt_labels);
    k_sample<<<2, 1024>>>(gt_ellipses);
    k_roi<<<NSAMP, 256>>>(features);
    k_splitT<<<dim3(32, 392), dim3(32, 8)>>>(w1, pw1h, pw1l, DIN);
    k_splitT<<<dim3(32, 32),  dim3(32, 8)>>>(w2, pw2h, pw2l, HID);
    k_gemm_mma<<<dim3(8, 8), 256, dyn_bytes>>>(pah, pal, pw1h, pw1l, b1,
                                               nullptr, px1h, px1l, DIN);
    k_gemm_mma<<<dim3(8, 8), 256, dyn_bytes>>>(px1h, px1l, pw2h, pw2l, b2,
                                               px2, nullptr, nullptr, HID);
    k_heads<<<NSAMP, 128>>>(wc, bc, wr, br);
    k_loss<<<1, 1024>>>(out);
}

// round 13
// speedup vs baseline: 2.0243x; 1.3516x over previous
#include <cuda_runtime.h>
#include <cuda_bf16.h>
#include <cstdint>

#define B_IMG   2
#define N_PROP  2000
#define N_GT    16
#define NPROPS  2016
#define C_FEAT  256
#define HF      128
#define WF      128
#define BPI     512
#define NPOS_MAX 128
#define HID     1024
#define DIN     12544
#define NSAMP   1024

// ---------------- device scratch ----------------
__device__ float g_props  [B_IMG * NPROPS * 4];
__device__ int   g_match  [B_IMG * NPROPS];
__device__ int   g_lab    [B_IMG * NPROPS];
__device__ float g_rand   [B_IMG * NPROPS];
__device__ float g_boxes  [NSAMP * 4];
__device__ int   g_labels [NSAMP];
__device__ float g_targets[NSAMP * 6];
__device__ __align__(16) __nv_bfloat16 g_ahi [NSAMP * DIN];
__device__ __align__(16) __nv_bfloat16 g_alo [NSAMP * DIN];
__device__ __align__(16) __nv_bfloat16 g_w1th[HID * DIN];
__device__ __align__(16) __nv_bfloat16 g_w1tl[HID * DIN];
__device__ __align__(16) __nv_bfloat16 g_x1h [NSAMP * HID];
__device__ __align__(16) __nv_bfloat16 g_x1l [NSAMP * HID];
__device__ __align__(16) __nv_bfloat16 g_w2th[HID * HID];
__device__ __align__(16) __nv_bfloat16 g_w2tl[HID * HID];
__device__ __align__(16) float g_x2[NSAMP * HID];
__device__ float g_logits [NSAMP * 2];
__device__ float g_reg    [NSAMP * 12];

// ---------------- helpers ----------------
__device__ __forceinline__ uint32_t smem_u32(const void* p) {
    uint32_t a;
    asm("{ .reg .u64 t; cvta.to.shared.u64 t, %1; cvt.u32.u64 %0, t; }" : "=r"(a) : "l"(p));
    return a;
}
__device__ __forceinline__ void cp16(uint32_t saddr, const void* g) {
    asm volatile("cp.async.cg.shared.global [%0], [%1], 16;" :: "r"(saddr), "l"(g));
}
__device__ __forceinline__ void ldsm4(uint32_t* r, uint32_t a) {
    asm volatile("ldmatrix.sync.aligned.m8n8.x4.shared.b16 {%0,%1,%2,%3}, [%4];"
                 : "=r"(r[0]), "=r"(r[1]), "=r"(r[2]), "=r"(r[3]) : "r"(a));
}
__device__ __forceinline__ void ldsm2(uint32_t* r, uint32_t a) {
    asm volatile("ldmatrix.sync.aligned.m8n8.x2.shared.b16 {%0,%1}, [%2];"
                 : "=r"(r[0]), "=r"(r[1]) : "r"(a));
}
__device__ __forceinline__ void mma_bf16(float* d, const uint32_t* a, const uint32_t* b) {
    asm volatile("mma.sync.aligned.m16n8k16.row.col.f32.bf16.bf16.f32 "
                 "{%0,%1,%2,%3},{%4,%5,%6,%7},{%8,%9},{%0,%1,%2,%3};"
                 : "+f"(d[0]), "+f"(d[1]), "+f"(d[2]), "+f"(d[3])
                 : "r"(a[0]), "r"(a[1]), "r"(a[2]), "r"(a[3]), "r"(b[0]), "r"(b[1]));
}
__device__ __forceinline__ void bf_split(float f, __nv_bfloat16& h, __nv_bfloat16& l) {
    h = __float2bfloat16_rn(f);
    l = __float2bfloat16_rn(f - __bfloat162float(h));
}

// ---------------- threefry2x32, key=(0,42), partitionable ----------------
__device__ __forceinline__ uint32_t rotl32(uint32_t x, int r) { return (x << r) | (x >> (32 - r)); }
__device__ __forceinline__ void threefry_0_42(uint32_t c0, uint32_t c1, uint32_t& o0, uint32_t& o1) {
    const uint32_t k0 = 0u, k1 = 42u, k2 = 0x1BD11BDAu ^ 42u;
    uint32_t x0 = c0 + k0, x1 = c1 + k1;
#define TFR(r) { x0 += x1; x1 = rotl32(x1, r); x1 ^= x0; }
    TFR(13) TFR(15) TFR(26) TFR(6)   x0 += k1; x1 += k2 + 1u;
    TFR(17) TFR(29) TFR(16) TFR(24)  x0 += k2; x1 += k0 + 2u;
    TFR(13) TFR(15) TFR(26) TFR(6)   x0 += k0; x1 += k1 + 3u;
    TFR(17) TFR(29) TFR(16) TFR(24)  x0 += k1; x1 += k2 + 4u;
    TFR(13) TFR(15) TFR(26) TFR(6)   x0 += k2; x1 += k0 + 5u;
#undef TFR
    o0 = x0; o1 = x1;
}

// ---------------- kernel 1: props + IoU + label + rand ----------------
__global__ void k_prep(const float* __restrict__ proposals,
                       const float* __restrict__ gt_boxes,
                       const int*   __restrict__ gt_labels) {
    int b = blockIdx.y;
    int p = blockIdx.x * blockDim.x + threadIdx.x;
    __shared__ float sg[N_GT * 4];
    __shared__ float sga[N_GT];
    __shared__ int   sgl[N_GT];
    if (threadIdx.x < N_GT) {
        int g = threadIdx.x;
        float gx1 = gt_boxes[(b * N_GT + g) * 4 + 0];
        float gy1 = gt_boxes[(b * N_GT + g) * 4 + 1];
        float gx2 = gt_boxes[(b * N_GT + g) * 4 + 2];
        float gy2 = gt_boxes[(b * N_GT + g) * 4 + 3];
        sg[g * 4 + 0] = gx1; sg[g * 4 + 1] = gy1;
        sg[g * 4 + 2] = gx2; sg[g * 4 + 3] = gy2;
        sga[g] = (gx2 - gx1) * (gy2 - gy1);
        sgl[g] = gt_labels[b * N_GT + g];
    }
    __syncthreads();
    if (p >= NPROPS) return;
    float px1, py1, px2, py2;
    if (p < N_PROP) {
        const float* pp = proposals + (size_t)(b * N_PROP + p) * 4;
        px1 = pp[0]; py1 = pp[1]; px2 = pp[2]; py2 = pp[3];
    } else {
        int g = p - N_PROP;
        px1 = sg[g * 4 + 0]; py1 = sg[g * 4 + 1];
        px2 = sg[g * 4 + 2]; py2 = sg[g * 4 + 3];
    }
    int n = b * NPROPS + p;
    g_props[n * 4 + 0] = px1; g_props[n * 4 + 1] = py1;
    g_props[n * 4 + 2] = px2; g_props[n * 4 + 3] = py2;
    float ap = (px2 - px1) * (py2 - py1);
    float best = -1.0f; int bi = 0;
#pragma unroll
    for (int g = 0; g < N_GT; g++) {
        float ltx = fmaxf(sg[g * 4 + 0], px1);
        float lty = fmaxf(sg[g * 4 + 1], py1);
        float rbx = fminf(sg[g * 4 + 2], px2);
        float rby = fminf(sg[g * 4 + 3], py2);
        float w = fmaxf(rbx - ltx, 0.0f);
        float h = fmaxf(rby - lty, 0.0f);
        float inter = w * h;
        float iou = inter / (sga[g] + ap - inter);
        if (iou > best) { best = iou; bi = g; }
    }
    g_match[n] = bi;
    g_lab[n]   = (best < 0.5f) ? 0 : sgl[bi];
    uint32_t o0, o1;
    threefry_0_42(0u, (uint32_t)n, o0, o1);
    uint32_t bits = o0 ^ o1;
    g_rand[n] = __uint_as_float((bits >> 9) | 0x3f800000u) - 1.0f;
}

// ---------------- kernel 2: sampling ----------------
__device__ __forceinline__ unsigned long long pack_key(float f, int i) {
    uint32_t u = __float_as_uint(f);
    u = (u & 0x80000000u) ? ~u : (u | 0x80000000u);
    return ((unsigned long long)u << 32) | (uint32_t)(0x7FF - i);
}
__device__ void bitonic_desc(unsigned long long* keys, int tid) {
    for (int k = 2; k <= 2048; k <<= 1)
        for (int j = k >> 1; j > 0; j >>= 1) {
            __syncthreads();
            for (int t = tid; t < 2048; t += 1024) {
                int ixj = t ^ j;
                if (ixj > t) {
                    unsigned long long a = keys[t], c = keys[ixj];
                    bool descBlk = ((t & k) == 0);
                    if (descBlk ? (a < c) : (a > c)) { keys[t] = c; keys[ixj] = a; }
                }
            }
        }
    __syncthreads();
}
__global__ __launch_bounds__(1024) void k_sample(const float* __restrict__ gt_ellipses) {
    int b = blockIdx.x, tid = threadIdx.x;
    __shared__ unsigned long long keys[2048];
    __shared__ unsigned char cap[2048];
    for (int i = tid; i < 2048; i += 1024) {
        cap[i] = 0;
        unsigned long long kv = 0ull;
        if (i < NPROPS) {
            float r = g_rand[b * NPROPS + i];
            float s = (g_lab[b * NPROPS + i] > 0) ? r : -1e9f;
            kv = pack_key(s, i);
        }
        keys[i] = kv;
    }
    __syncthreads();
    bitonic_desc(keys, tid);
    if (tid < NPOS_MAX) {
        unsigned long long kv = keys[tid];
        if (kv) {
            int i = 0x7FF - (int)(uint32_t)(kv & 0xFFFFFFFFull);
            if (i >= 0 && i < NPROPS && g_lab[b * NPROPS + i] > 0) cap[i] = 1;
        }
    }
    __syncthreads();
    for (int i = tid; i < 2048; i += 1024) {
        unsigned long long kv = 0ull;
        if (i < NPROPS) {
            float r = g_rand[b * NPROPS + i];
            float prio = cap[i] ? (r + 2.0f)
                                : ((g_lab[b * NPROPS + i] == 0) ? r : -1e9f);
            kv = pack_key(prio, i);
        }
        keys[i] = kv;
    }
    __syncthreads();
    bitonic_desc(keys, tid);
    if (tid < BPI) {
        int i   = 0x7FF - (int)(uint32_t)(keys[tid] & 0xFFFFFFFFull);
        int n   = b * BPI + tid;
        int src = b * NPROPS + i;
        float x1 = g_props[src * 4 + 0], y1 = g_props[src * 4 + 1];
        float x2 = g_props[src * 4 + 2], y2 = g_props[src * 4 + 3];
        g_boxes[n * 4 + 0] = x1; g_boxes[n * 4 + 1] = y1;
        g_boxes[n * 4 + 2] = x2; g_boxes[n * 4 + 3] = y2;
        int lab = g_lab[src];
        g_labels[n] = lab;
        int m = g_match[src];
        const float* el = gt_ellipses + (size_t)(b * N_GT + m) * 5;
        float ea = el[0], eb = el[1], ex = el[2], ey = el[3], th = el[4];
        float w  = fmaxf(x2 - x1, 1.0f), h = fmaxf(y2 - y1, 1.0f);
        float cx = 0.5f * (x1 + x2),    cy = 0.5f * (y1 + y2);
        g_targets[n * 6 + 0] = (ex - cx) / w;
        g_targets[n * 6 + 1] = (ey - cy) / h;
        g_targets[n * 6 + 2] = logf(fmaxf(2.0f * ea, 0.001f) / w);
        g_targets[n * 6 + 3] = logf(fmaxf(2.0f * eb, 0.001f) / h);
        g_targets[n * 6 + 4] = sinf(2.0f * th);
        g_targets[n * 6 + 5] = cosf(2.0f * th);
    }
}

// ---------------- kernel 3: RoI-align -> split bf16 ----------------
__global__ __launch_bounds__(256) void k_roi(const float* __restrict__ features) {
    int n   = blockIdx.x;
    int b   = n >> 9;
    int tid = threadIdx.x;
    __shared__ int   sy0[14], sx0[14];
    __shared__ float sly[14], slx[14];
    if (tid < 28) {
        float bx1 = g_boxes[n * 4 + 0] * 0.125f;
        float by1 = g_boxes[n * 4 + 1] * 0.125f;
        float bx2 = g_boxes[n * 4 + 2] * 0.125f;
        float by2 = g_boxes[n * 4 + 3] * 0.125f;
        float bw = fmaxf(bx2 - bx1, 1.0f) / 7.0f;
        float bh = fmaxf(by2 - by1, 1.0f) / 7.0f;
        if (tid < 14) {
            float off = ((float)tid + 0.5f) / 2.0f;
            float ys = fminf(fmaxf(by1 + off * bh, 0.0f), 127.0f);
            int y0 = (int)floorf(ys); y0 = min(max(y0, 0), 126);
            sy0[tid] = y0; sly[tid] = ys - (float)y0;
        } else {
            int i = tid - 14;
            float off = ((float)i + 0.5f) / 2.0f;
            float xs = fminf(fmaxf(bx1 + off * bw, 0.0f), 127.0f);
            int x0 = (int)floorf(xs); x0 = min(max(x0, 0), 126);
            sx0[i] = x0; slx[i] = xs - (float)x0;
        }
    }
    __syncthreads();
    const float* fb = features + (size_t)b * C_FEAT * HF * WF;
    for (int it = 0; it < 49; it++) {
        int e = it * 256 + tid;
        int c = e / 49;
        int r = e - c * 49;
        int py = r / 7, px = r - py * 7;
        const float* fc = fb + (size_t)c * (HF * WF);
        float acc = 0.0f;
#pragma unroll
        for (int sy = 0; sy < 2; sy++) {
            int i = py * 2 + sy;
            int y0 = sy0[i]; float fy = sly[i];
            const float* rowp = fc + y0 * WF;
#pragma unroll
            for (int sx = 0; sx < 2; sx++) {
                int j = px * 2 + sx;
                int x0 = sx0[j]; float fx = slx[j];
                float v00 = __ldg(rowp + x0);
                float v01 = __ldg(rowp + x0 + 1);
                float v10 = __ldg(rowp + WF + x0);
                float v11 = __ldg(rowp + WF + x0 + 1);
                float top = v00 + (v01 - v00) * fx;
                float bot = v10 + (v11 - v10) * fx;
                acc += top + (bot - top) * fy;
            }
        }
        float v = acc * 0.25f;
        __nv_bfloat16 h, l; bf_split(v, h, l);
        g_ahi[(size_t)n * DIN + e] = h;
        g_alo[(size_t)n * DIN + e] = l;
    }
}

// ---------------- transpose + split weights: out[n][k] = split(in[k][n]) ----------------
__global__ void k_splitT(const float* __restrict__ in,
                         __nv_bfloat16* __restrict__ oh,
                         __nv_bfloat16* __restrict__ ol, int K) {
    __shared__ float t[32][33];
    int nb = blockIdx.x * 32, kb = blockIdx.y * 32;
    int tx = threadIdx.x, ty = threadIdx.y;
#pragma unroll
    for (int r = 0; r < 4; r++)
        t[ty + r * 8][tx] = in[(size_t)(kb + ty + r * 8) * HID + nb + tx];
    __syncthreads();
#pragma unroll
    for (int r = 0; r < 4; r++) {
        int n = nb + ty + r * 8;
        float f = t[tx][ty + r * 8];
        __nv_bfloat16 h, l; bf_split(f, h, l);
        oh[(size_t)n * K + kb + tx] = h;
        ol[(size_t)n * K + kb + tx] = l;
    }
}

// ---------------- HMMA split-bf16 GEMM + bias + ReLU ----------------
// C[1024,1024] = relu(A @ B^T + bias); A[M][K], B[N][K] hi/lo bf16.
// CTA 128(M) x 64(N), 8 warps (2x4), warp tile 64x16, BK=32, 2-stage cp.async.
// grid = (N/64, M/128) = (16, 8) -> 128 CTAs (one full wave on 148 SMs).
#define ROWPAD 40                     // bf16 per smem row (80 B, conflict-free ldmatrix)
#define TILE_AB (128 * ROWPAD * 2)    // 10240 B (A hi or lo)
#define TILE_BB (64 * ROWPAD * 2)     // 5120 B  (B hi or lo)
#define OFF_AL  TILE_AB
#define OFF_BH  (2 * TILE_AB)
#define OFF_BL  (2 * TILE_AB + TILE_BB)
#define STAGE_B (2 * TILE_AB + 2 * TILE_BB)   // 30720 B
__global__ __launch_bounds__(256, 1) void k_gemm_mma(
    const __nv_bfloat16* __restrict__ Ah, const __nv_bfloat16* __restrict__ Al,
    const __nv_bfloat16* __restrict__ Bh, const __nv_bfloat16* __restrict__ Bl,
    const float* __restrict__ bias,
    float* __restrict__ Cf, __nv_bfloat16* __restrict__ Ch, __nv_bfloat16* __restrict__ Cl,
    int K)
{
    extern __shared__ char sm[];
    uint32_t sbase = smem_u32(sm);
    int tid = threadIdx.x, wid = tid >> 5, lane = tid & 31;
    int wm = wid >> 2, wn = wid & 3;              // 2 x 4 warp grid
    int m0 = blockIdx.y << 7, n0 = blockIdx.x << 6;

    float acc[4][2][4];
#pragma unroll
    for (int i = 0; i < 4; i++)
#pragma unroll
        for (int j = 0; j < 2; j++)
#pragma unroll
            for (int q = 0; q < 4; q++) acc[i][j][q] = 0.0f;

    int nsteps = K >> 5;

    // per stage: A = 512 16B-chunks (2/thread) for each of hi/lo; B = 256 (1/thread)
#define LOAD_STAGE(st, k0)                                                  \
    {                                                                       \
        uint32_t sb = sbase + (uint32_t)(st) * STAGE_B;                     \
        _Pragma("unroll")                                                   \
        for (int i = 0; i < 2; i++) {                                       \
            int c   = tid + (i << 8);                                       \
            int row = c >> 2, cc = c & 3;                                   \
            uint32_t so = (uint32_t)(row * (ROWPAD * 2) + cc * 16);         \
            size_t goA = (size_t)(m0 + row) * K + (k0) + cc * 8;            \
            cp16(sb + so,          Ah + goA);                               \
            cp16(sb + OFF_AL + so, Al + goA);                               \
        }                                                                   \
        {                                                                   \
            int row = tid >> 2, cc = tid & 3;                               \
            uint32_t so = (uint32_t)(row * (ROWPAD * 2) + cc * 16);         \
            size_t goB = (size_t)(n0 + row) * K + (k0) + cc * 8;            \
            cp16(sb + OFF_BH + so, Bh + goB);                               \
            cp16(sb + OFF_BL + so, Bl + goB);                               \
        }                                                                   \
        asm volatile("cp.async.commit_group;" ::: "memory");                \
    }

    LOAD_STAGE(0, 0)

    for (int s = 0; s < nsteps; s++) {
        if (s + 1 < nsteps) {
            LOAD_STAGE((s + 1) & 1, (s + 1) << 5)
            asm volatile("cp.async.wait_group 1;" ::: "memory");
        } else {
            asm volatile("cp.async.wait_group 0;" ::: "memory");
        }
        __syncthreads();

        uint32_t sb = sbase + (uint32_t)(s & 1) * STAGE_B;
#pragma unroll
        for (int kc = 0; kc < 2; kc++) {
            uint32_t ah[4][4], al[4][4], bh[2][2], bl[2][2];
            int arow = wm * 64 + (lane & 7) + ((lane >> 3) & 1) * 8;
            int acol = kc * 16 + ((lane >> 4) & 1) * 8;
#pragma unroll
            for (int mi = 0; mi < 4; mi++) {
                uint32_t ad = sb + (uint32_t)((arow + mi * 16) * (ROWPAD * 2) + acol * 2);
                ldsm4(ah[mi], ad);
                ldsm4(al[mi], ad + OFF_AL);
            }
            int brow = wn * 16 + (lane & 7);
            int bcol = kc * 16 + ((lane >> 3) & 1) * 8;
#pragma unroll
            for (int ni = 0; ni < 2; ni++) {
                uint32_t bd = sb + OFF_BH + (uint32_t)((brow + ni * 8) * (ROWPAD * 2) + bcol * 2);
                ldsm2(bh[ni], bd);
                ldsm2(bl[ni], bd + TILE_BB);
            }
#pragma unroll
            for (int mi = 0; mi < 4; mi++)
#pragma unroll
                for (int ni = 0; ni < 2; ni++) {
                    mma_bf16(acc[mi][ni], ah[mi], bh[ni]);
                    mma_bf16(acc[mi][ni], al[mi], bh[ni]);
                    mma_bf16(acc[mi][ni], ah[mi], bl[ni]);
                }
        }
        __syncthreads();
    }

    // epilogue: c0,c1 -> row r, cols 2c,2c+1 ; c2,c3 -> row r+8
    int r = lane >> 2, cp = (lane & 3) * 2;
#pragma unroll
    for (int mi = 0; mi < 4; mi++) {
        int mA = m0 + wm * 64 + mi * 16 + r;
        int mB = mA + 8;
#pragma unroll
        for (int ni = 0; ni < 2; ni++) {
            int n = n0 + wn * 16 + ni * 8 + cp;
            float b0v = __ldg(bias + n), b1v = __ldg(bias + n + 1);
            float* a = acc[mi][ni];
            float v00 = fmaxf(a[0] + b0v, 0.f), v01 = fmaxf(a[1] + b1v, 0.f);
            float v10 = fmaxf(a[2] + b0v, 0.f), v11 = fmaxf(a[3] + b1v, 0.f);
            if (Cf) {
                *(float2*)(Cf + (size_t)mA * 1024 + n) = make_float2(v00, v01);
                *(float2*)(Cf + (size_t)mB * 1024 + n) = make_float2(v10, v11);
            } else {
                __nv_bfloat16 h0, l0, h1, l1;
                bf_split(v00, h0, l0); bf_split(v01, h1, l1);
                *(ushort2*)(Ch + (size_t)mA * 1024 + n) =
                    make_ushort2(__bfloat16_as_ushort(h0), __bfloat16_as_ushort(h1));
                *(ushort2*)(Cl + (size_t)mA * 1024 + n) =
                    make_ushort2(__bfloat16_as_ushort(l0), __bfloat16_as_ushort(l1));
                bf_split(v10, h0, l0); bf_split(v11, h1, l1);
                *(ushort2*)(Ch + (size_t)mB * 1024 + n) =
                    make_ushort2(__bfloat16_as_ushort(h0), __bfloat16_as_ushort(h1));
                *(ushort2*)(Cl + (size_t)mB * 1024 + n) =
                    make_ushort2(__bfloat16_as_ushort(l0), __bfloat16_as_ushort(l1));
            }
        }
    }
}

// ---------------- heads ----------------
__global__ __launch_bounds__(128) void k_heads(const float* __restrict__ wc,
                                               const float* __restrict__ bc,
                                               const float* __restrict__ wr,
                                               const float* __restrict__ br) {
    int n = blockIdx.x, tid = threadIdx.x;
    float acc[14];
#pragma unroll
    for (int o = 0; o < 14; o++) acc[o] = 0.0f;
    const float* xr = g_x2 + (size_t)n * HID;
    for (int k = tid; k < HID; k += 128) {
        float xv = xr[k];
        acc[0] = fmaf(xv, wc[k * 2 + 0], acc[0]);
        acc[1] = fmaf(xv, wc[k * 2 + 1], acc[1]);
#pragma unroll
        for (int j = 0; j < 12; j++)
            acc[2 + j] = fmaf(xv, wr[k * 12 + j], acc[2 + j]);
    }
    __shared__ float sh[128];
    for (int o = 0; o < 14; o++) {
        sh[tid] = acc[o]; __syncthreads();
        for (int s = 64; s > 0; s >>= 1) {
            if (tid < s) sh[tid] += sh[tid + s];
            __syncthreads();
        }
        if (tid == 0) {
            float v = sh[0] + (o < 2 ? bc[o] : br[o - 2]);
            if (o < 2) g_logits[n * 2 + o] = v;
            else       g_reg[n * 12 + (o - 2)] = v;
        }
        __syncthreads();
    }
}

// ---------------- losses ----------------
__global__ __launch_bounds__(1024) void k_loss(float* __restrict__ out) {
    int tid = threadIdx.x;
    const float BETA = 1.0f / 9.0f;
    float l0 = g_logits[tid * 2 + 0], l1 = g_logits[tid * 2 + 1];
    int lab = g_labels[tid];
    float mx  = fmaxf(l0, l1);
    float lse = mx + logf(expf(l0 - mx) + expf(l1 - mx));
    float ce  = lse - g_logits[tid * 2 + lab];
    float rl = 0.0f;
    if (lab > 0) {
        const float* pr = g_reg + tid * 12 + lab * 6;
        const float* tg = g_targets + tid * 6;
#pragma unroll
        for (int j = 0; j < 6; j++) {
            float d = fabsf(pr[j] - tg[j]);
            rl += (d < BETA) ? (0.5f * d * d / BETA) : (d - 0.5f * BETA);
        }
    }
    __shared__ float sce[1024];
    __shared__ float srl[1024];
    sce[tid] = ce; srl[tid] = rl;
    __syncthreads();
    for (int s = 512; s > 0; s >>= 1) {
        if (tid < s) { sce[tid] += sce[tid + s]; srl[tid] += srl[tid + s]; }
        __syncthreads();
    }
    if (tid == 0) {
        out[0] = sce[0] / (float)NSAMP;
        out[1] = srl[0] / (float)NSAMP;
    }
}

// ---------------- launch ----------------
extern "C" void kernel_launch(void* const* d_in, const int* in_sizes, int n_in,
                              void* d_out, int out_size) {
    const float* features    = (const float*)d_in[0];
    const float* proposals   = (const float*)d_in[1];
    const float* gt_boxes    = (const float*)d_in[2];
    const int*   gt_labels   = (const int*)  d_in[3];
    const float* gt_ellipses = (const float*)d_in[4];
    const float* w1 = (const float*)d_in[5];
    const float* b1 = (const float*)d_in[6];
    const float* w2 = (const float*)d_in[7];
    const float* b2 = (const float*)d_in[8];
    const float* wc = (const float*)d_in[9];
    const float* bc = (const float*)d_in[10];
    const float* wr = (const float*)d_in[11];
    const float* br = (const float*)d_in[12];
    float* out = (float*)d_out;

    __nv_bfloat16 *pah, *pal, *pw1h, *pw1l, *px1h, *px1l, *pw2h, *pw2l;
    float *px2;
    cudaGetSymbolAddress((void**)&pah,  g_ahi);
    cudaGetSymbolAddress((void**)&pal,  g_alo);
    cudaGetSymbolAddress((void**)&pw1h, g_w1th);
    cudaGetSymbolAddress((void**)&pw1l, g_w1tl);
    cudaGetSymbolAddress((void**)&px1h, g_x1h);
    cudaGetSymbolAddress((void**)&px1l, g_x1l);
    cudaGetSymbolAddress((void**)&pw2h, g_w2th);
    cudaGetSymbolAddress((void**)&pw2l, g_w2tl);
    cudaGetSymbolAddress((void**)&px2,  g_x2);

    const int dyn_bytes = 2 * STAGE_B;   // 61440
    cudaFuncSetAttribute(k_gemm_mma, cudaFuncAttributeMaxDynamicSharedMemorySize, dyn_bytes);

    k_prep<<<dim3(8, 2), 256>>>(proposals, gt_boxes, gt_labels);
    k_sample<<<2, 1024>>>(gt_ellipses);
    k_roi<<<NSAMP, 256>>>(features);
    k_splitT<<<dim3(32, 392), dim3(32, 8)>>>(w1, pw1h, pw1l, DIN);
    k_splitT<<<dim3(32, 32),  dim3(32, 8)>>>(w2, pw2h, pw2l, HID);
    k_gemm_mma<<<dim3(16, 8), 256, dyn_bytes>>>(pah, pal, pw1h, pw1l, b1,
                                                nullptr, px1h, px1l, DIN);
    k_gemm_mma<<<dim3(16, 8), 256, dyn_bytes>>>(px1h, px1l, pw2h, pw2l, b2,
                                                px2, nullptr, nullptr, HID);
    k_heads<<<NSAMP, 128>>>(wc, bc, wr, br);
    k_loss<<<1, 1024>>>(out);
}

// round 14
// speedup vs baseline: 2.3297x; 1.1509x over previous
#include <cuda_runtime.h>
#include <cuda_bf16.h>
#include <cstdint>

#define B_IMG   2
#define N_PROP  2000
#define N_GT    16
#define NPROPS  2016
#define C_FEAT  256
#define HF      128
#define WF      128
#define BPI     512
#define NPOS_MAX 128
#define HID     1024
#define DIN     12544
#define NSAMP   1024

// ---------------- device scratch ----------------
__device__ float g_props  [B_IMG * NPROPS * 4];
__device__ int   g_match  [B_IMG * NPROPS];
__device__ int   g_lab    [B_IMG * NPROPS];
__device__ float g_rand   [B_IMG * NPROPS];
__device__ float g_boxes  [NSAMP * 4];
__device__ int   g_labels [NSAMP];
__device__ float g_targets[NSAMP * 6];
__device__ __align__(16) __nv_bfloat16 g_ahi [NSAMP * DIN];
__device__ __align__(16) __nv_bfloat16 g_alo [NSAMP * DIN];
__device__ __align__(16) __nv_bfloat16 g_w1th[HID * DIN];
__device__ __align__(16) __nv_bfloat16 g_w1tl[HID * DIN];
__device__ __align__(16) __nv_bfloat16 g_x1h [NSAMP * HID];
__device__ __align__(16) __nv_bfloat16 g_x1l [NSAMP * HID];
__device__ __align__(16) __nv_bfloat16 g_w2th[HID * HID];
__device__ __align__(16) __nv_bfloat16 g_w2tl[HID * HID];
__device__ __align__(16) float g_x2[NSAMP * HID];
__device__ float g_logits [NSAMP * 2];
__device__ float g_reg    [NSAMP * 12];

// ---------------- helpers ----------------
__device__ __forceinline__ uint32_t smem_u32(const void* p) {
    uint32_t a;
    asm("{ .reg .u64 t; cvta.to.shared.u64 t, %1; cvt.u32.u64 %0, t; }" : "=r"(a) : "l"(p));
    return a;
}
__device__ __forceinline__ void cp16(uint32_t saddr, const void* g) {
    asm volatile("cp.async.cg.shared.global [%0], [%1], 16;" :: "r"(saddr), "l"(g));
}
__device__ __forceinline__ void ldsm4(uint32_t* r, uint32_t a) {
    asm volatile("ldmatrix.sync.aligned.m8n8.x4.shared.b16 {%0,%1,%2,%3}, [%4];"
                 : "=r"(r[0]), "=r"(r[1]), "=r"(r[2]), "=r"(r[3]) : "r"(a));
}
__device__ __forceinline__ void ldsm2(uint32_t* r, uint32_t a) {
    asm volatile("ldmatrix.sync.aligned.m8n8.x2.shared.b16 {%0,%1}, [%2];"
                 : "=r"(r[0]), "=r"(r[1]) : "r"(a));
}
__device__ __forceinline__ void mma_bf16(float* d, const uint32_t* a, const uint32_t* b) {
    asm volatile("mma.sync.aligned.m16n8k16.row.col.f32.bf16.bf16.f32 "
                 "{%0,%1,%2,%3},{%4,%5,%6,%7},{%8,%9},{%0,%1,%2,%3};"
                 : "+f"(d[0]), "+f"(d[1]), "+f"(d[2]), "+f"(d[3])
                 : "r"(a[0]), "r"(a[1]), "r"(a[2]), "r"(a[3]), "r"(b[0]), "r"(b[1]));
}
__device__ __forceinline__ void bf_split(float f, __nv_bfloat16& h, __nv_bfloat16& l) {
    h = __float2bfloat16_rn(f);
    l = __float2bfloat16_rn(f - __bfloat162float(h));
}

// ---------------- threefry2x32, key=(0,42), partitionable ----------------
__device__ __forceinline__ uint32_t rotl32(uint32_t x, int r) { return (x << r) | (x >> (32 - r)); }
__device__ __forceinline__ void threefry_0_42(uint32_t c0, uint32_t c1, uint32_t& o0, uint32_t& o1) {
    const uint32_t k0 = 0u, k1 = 42u, k2 = 0x1BD11BDAu ^ 42u;
    uint32_t x0 = c0 + k0, x1 = c1 + k1;
#define TFR(r) { x0 += x1; x1 = rotl32(x1, r); x1 ^= x0; }
    TFR(13) TFR(15) TFR(26) TFR(6)   x0 += k1; x1 += k2 + 1u;
    TFR(17) TFR(29) TFR(16) TFR(24)  x0 += k2; x1 += k0 + 2u;
    TFR(13) TFR(15) TFR(26) TFR(6)   x0 += k0; x1 += k1 + 3u;
    TFR(17) TFR(29) TFR(16) TFR(24)  x0 += k1; x1 += k2 + 4u;
    TFR(13) TFR(15) TFR(26) TFR(6)   x0 += k2; x1 += k0 + 5u;
#undef TFR
    o0 = x0; o1 = x1;
}

// ---------------- kernel 1: props + IoU + label + rand ----------------
__global__ void k_prep(const float* __restrict__ proposals,
                       const float* __restrict__ gt_boxes,
                       const int*   __restrict__ gt_labels) {
    int b = blockIdx.y;
    int p = blockIdx.x * blockDim.x + threadIdx.x;
    __shared__ float sg[N_GT * 4];
    __shared__ float sga[N_GT];
    __shared__ int   sgl[N_GT];
    if (threadIdx.x < N_GT) {
        int g = threadIdx.x;
        float gx1 = gt_boxes[(b * N_GT + g) * 4 + 0];
        float gy1 = gt_boxes[(b * N_GT + g) * 4 + 1];
        float gx2 = gt_boxes[(b * N_GT + g) * 4 + 2];
        float gy2 = gt_boxes[(b * N_GT + g) * 4 + 3];
        sg[g * 4 + 0] = gx1; sg[g * 4 + 1] = gy1;
        sg[g * 4 + 2] = gx2; sg[g * 4 + 3] = gy2;
        sga[g] = (gx2 - gx1) * (gy2 - gy1);
        sgl[g] = gt_labels[b * N_GT + g];
    }
    __syncthreads();
    if (p >= NPROPS) return;
    float px1, py1, px2, py2;
    if (p < N_PROP) {
        const float* pp = proposals + (size_t)(b * N_PROP + p) * 4;
        px1 = pp[0]; py1 = pp[1]; px2 = pp[2]; py2 = pp[3];
    } else {
        int g = p - N_PROP;
        px1 = sg[g * 4 + 0]; py1 = sg[g * 4 + 1];
        px2 = sg[g * 4 + 2]; py2 = sg[g * 4 + 3];
    }
    int n = b * NPROPS + p;
    g_props[n * 4 + 0] = px1; g_props[n * 4 + 1] = py1;
    g_props[n * 4 + 2] = px2; g_props[n * 4 + 3] = py2;
    float ap = (px2 - px1) * (py2 - py1);
    float best = -1.0f; int bi = 0;
#pragma unroll
    for (int g = 0; g < N_GT; g++) {
        float ltx = fmaxf(sg[g * 4 + 0], px1);
        float lty = fmaxf(sg[g * 4 + 1], py1);
        float rbx = fminf(sg[g * 4 + 2], px2);
        float rby = fminf(sg[g * 4 + 3], py2);
        float w = fmaxf(rbx - ltx, 0.0f);
        float h = fmaxf(rby - lty, 0.0f);
        float inter = w * h;
        float iou = inter / (sga[g] + ap - inter);
        if (iou > best) { best = iou; bi = g; }
    }
    g_match[n] = bi;
    g_lab[n]   = (best < 0.5f) ? 0 : sgl[bi];
    uint32_t o0, o1;
    threefry_0_42(0u, (uint32_t)n, o0, o1);
    uint32_t bits = o0 ^ o1;
    g_rand[n] = __uint_as_float((bits >> 9) | 0x3f800000u) - 1.0f;
}

// ---------------- kernel 2: sampling ----------------
__device__ __forceinline__ unsigned long long pack_key(float f, int i) {
    uint32_t u = __float_as_uint(f);
    u = (u & 0x80000000u) ? ~u : (u | 0x80000000u);
    return ((unsigned long long)u << 32) | (uint32_t)(0x7FF - i);
}
__device__ void bitonic_desc(unsigned long long* keys, int tid) {
    for (int k = 2; k <= 2048; k <<= 1)
        for (int j = k >> 1; j > 0; j >>= 1) {
            __syncthreads();
            for (int t = tid; t < 2048; t += 1024) {
                int ixj = t ^ j;
                if (ixj > t) {
                    unsigned long long a = keys[t], c = keys[ixj];
                    bool descBlk = ((t & k) == 0);
                    if (descBlk ? (a < c) : (a > c)) { keys[t] = c; keys[ixj] = a; }
                }
            }
        }
    __syncthreads();
}
__global__ __launch_bounds__(1024) void k_sample(const float* __restrict__ gt_ellipses) {
    int b = blockIdx.x, tid = threadIdx.x;
    __shared__ unsigned long long keys[2048];
    __shared__ unsigned char cap[2048];
    for (int i = tid; i < 2048; i += 1024) {
        cap[i] = 0;
        unsigned long long kv = 0ull;
        if (i < NPROPS) {
            float r = g_rand[b * NPROPS + i];
            float s = (g_lab[b * NPROPS + i] > 0) ? r : -1e9f;
            kv = pack_key(s, i);
        }
        keys[i] = kv;
    }
    __syncthreads();
    bitonic_desc(keys, tid);
    if (tid < NPOS_MAX) {
        unsigned long long kv = keys[tid];
        if (kv) {
            int i = 0x7FF - (int)(uint32_t)(kv & 0xFFFFFFFFull);
            if (i >= 0 && i < NPROPS && g_lab[b * NPROPS + i] > 0) cap[i] = 1;
        }
    }
    __syncthreads();
    for (int i = tid; i < 2048; i += 1024) {
        unsigned long long kv = 0ull;
        if (i < NPROPS) {
            float r = g_rand[b * NPROPS + i];
            float prio = cap[i] ? (r + 2.0f)
                                : ((g_lab[b * NPROPS + i] == 0) ? r : -1e9f);
            kv = pack_key(prio, i);
        }
        keys[i] = kv;
    }
    __syncthreads();
    bitonic_desc(keys, tid);
    if (tid < BPI) {
        int i   = 0x7FF - (int)(uint32_t)(keys[tid] & 0xFFFFFFFFull);
        int n   = b * BPI + tid;
        int src = b * NPROPS + i;
        float x1 = g_props[src * 4 + 0], y1 = g_props[src * 4 + 1];
        float x2 = g_props[src * 4 + 2], y2 = g_props[src * 4 + 3];
        g_boxes[n * 4 + 0] = x1; g_boxes[n * 4 + 1] = y1;
        g_boxes[n * 4 + 2] = x2; g_boxes[n * 4 + 3] = y2;
        int lab = g_lab[src];
        g_labels[n] = lab;
        int m = g_match[src];
        const float* el = gt_ellipses + (size_t)(b * N_GT + m) * 5;
        float ea = el[0], eb = el[1], ex = el[2], ey = el[3], th = el[4];
        float w  = fmaxf(x2 - x1, 1.0f), h = fmaxf(y2 - y1, 1.0f);
        float cx = 0.5f * (x1 + x2),    cy = 0.5f * (y1 + y2);
        g_targets[n * 6 + 0] = (ex - cx) / w;
        g_targets[n * 6 + 1] = (ey - cy) / h;
        g_targets[n * 6 + 2] = logf(fmaxf(2.0f * ea, 0.001f) / w);
        g_targets[n * 6 + 3] = logf(fmaxf(2.0f * eb, 0.001f) / h);
        g_targets[n * 6 + 4] = sinf(2.0f * th);
        g_targets[n * 6 + 5] = cosf(2.0f * th);
    }
}

// ---------------- kernel 3: RoI-align -> split bf16 ----------------
__global__ __launch_bounds__(256) void k_roi(const float* __restrict__ features) {
    int n   = blockIdx.x;
    int b   = n >> 9;
    int tid = threadIdx.x;
    __shared__ int   sy0[14], sx0[14];
    __shared__ float sly[14], slx[14];
    if (tid < 28) {
        float bx1 = g_boxes[n * 4 + 0] * 0.125f;
        float by1 = g_boxes[n * 4 + 1] * 0.125f;
        float bx2 = g_boxes[n * 4 + 2] * 0.125f;
        float by2 = g_boxes[n * 4 + 3] * 0.125f;
        float bw = fmaxf(bx2 - bx1, 1.0f) / 7.0f;
        float bh = fmaxf(by2 - by1, 1.0f) / 7.0f;
        if (tid < 14) {
            float off = ((float)tid + 0.5f) / 2.0f;
            float ys = fminf(fmaxf(by1 + off * bh, 0.0f), 127.0f);
            int y0 = (int)floorf(ys); y0 = min(max(y0, 0), 126);
            sy0[tid] = y0; sly[tid] = ys - (float)y0;
        } else {
            int i = tid - 14;
            float off = ((float)i + 0.5f) / 2.0f;
            float xs = fminf(fmaxf(bx1 + off * bw, 0.0f), 127.0f);
            int x0 = (int)floorf(xs); x0 = min(max(x0, 0), 126);
            sx0[i] = x0; slx[i] = xs - (float)x0;
        }
    }
    __syncthreads();
    const float* fb = features + (size_t)b * C_FEAT * HF * WF;
    for (int it = 0; it < 49; it++) {
        int e = it * 256 + tid;
        int c = e / 49;
        int r = e - c * 49;
        int py = r / 7, px = r - py * 7;
        const float* fc = fb + (size_t)c * (HF * WF);
        float acc = 0.0f;
#pragma unroll
        for (int sy = 0; sy < 2; sy++) {
            int i = py * 2 + sy;
            int y0 = sy0[i]; float fy = sly[i];
            const float* rowp = fc + y0 * WF;
#pragma unroll
            for (int sx = 0; sx < 2; sx++) {
                int j = px * 2 + sx;
                int x0 = sx0[j]; float fx = slx[j];
                float v00 = __ldg(rowp + x0);
                float v01 = __ldg(rowp + x0 + 1);
                float v10 = __ldg(rowp + WF + x0);
                float v11 = __ldg(rowp + WF + x0 + 1);
                float top = v00 + (v01 - v00) * fx;
                float bot = v10 + (v11 - v10) * fx;
                acc += top + (bot - top) * fy;
            }
        }
        float v = acc * 0.25f;
        __nv_bfloat16 h, l; bf_split(v, h, l);
        g_ahi[(size_t)n * DIN + e] = h;
        g_alo[(size_t)n * DIN + e] = l;
    }
}

// ---------------- transpose + split weights: out[n][k] = split(in[k][n]) ----------------
__global__ void k_splitT(const float* __restrict__ in,
                         __nv_bfloat16* __restrict__ oh,
                         __nv_bfloat16* __restrict__ ol, int K) {
    __shared__ float t[32][33];
    int nb = blockIdx.x * 32, kb = blockIdx.y * 32;
    int tx = threadIdx.x, ty = threadIdx.y;
#pragma unroll
    for (int r = 0; r < 4; r++)
        t[ty + r * 8][tx] = in[(size_t)(kb + ty + r * 8) * HID + nb + tx];
    __syncthreads();
#pragma unroll
    for (int r = 0; r < 4; r++) {
        int n = nb + ty + r * 8;
        float f = t[tx][ty + r * 8];
        __nv_bfloat16 h, l; bf_split(f, h, l);
        oh[(size_t)n * K + kb + tx] = h;
        ol[(size_t)n * K + kb + tx] = l;
    }
}

// ---------------- HMMA split-bf16 GEMM + bias + ReLU (2-term) ----------------
// C = relu(A @ B^T + bias); terms: Ah*Bh + Al*Bh  (A error fully compensated,
// B bf16-rounded; dropped Ah*Bl term ~1.1e-3 per element, ~1e-4 on final scalars).
// CTA 128(M) x 64(N), 8 warps (2x4), warp tile 64x16, BK=32, 2-stage cp.async.
// grid = (16, 8) -> 128 CTAs (one wave on 148 SMs). B-lo never loaded.
#define ROWPAD 40                     // bf16 per smem row (80 B, conflict-free ldmatrix)
#define TILE_AB (128 * ROWPAD * 2)    // 10240 B (A hi or lo)
#define TILE_BB (64 * ROWPAD * 2)     // 5120 B  (B hi)
#define OFF_AL  TILE_AB
#define OFF_BH  (2 * TILE_AB)
#define STAGE_B (2 * TILE_AB + TILE_BB)   // 25600 B
__global__ __launch_bounds__(256, 1) void k_gemm_mma(
    const __nv_bfloat16* __restrict__ Ah, const __nv_bfloat16* __restrict__ Al,
    const __nv_bfloat16* __restrict__ Bh,
    const float* __restrict__ bias,
    float* __restrict__ Cf, __nv_bfloat16* __restrict__ Ch, __nv_bfloat16* __restrict__ Cl,
    int K)
{
    extern __shared__ char sm[];
    uint32_t sbase = smem_u32(sm);
    int tid = threadIdx.x, wid = tid >> 5, lane = tid & 31;
    int wm = wid >> 2, wn = wid & 3;              // 2 x 4 warp grid
    int m0 = blockIdx.y << 7, n0 = blockIdx.x << 6;

    float acc[4][2][4];
#pragma unroll
    for (int i = 0; i < 4; i++)
#pragma unroll
        for (int j = 0; j < 2; j++)
#pragma unroll
            for (int q = 0; q < 4; q++) acc[i][j][q] = 0.0f;

    int nsteps = K >> 5;

#define LOAD_STAGE(st, k0)                                                  \
    {                                                                       \
        uint32_t sb = sbase + (uint32_t)(st) * STAGE_B;                     \
        _Pragma("unroll")                                                   \
        for (int i = 0; i < 2; i++) {                                       \
            int c   = tid + (i << 8);                                       \
            int row = c >> 2, cc = c & 3;                                   \
            uint32_t so = (uint32_t)(row * (ROWPAD * 2) + cc * 16);         \
            size_t goA = (size_t)(m0 + row) * K + (k0) + cc * 8;            \
            cp16(sb + so,          Ah + goA);                               \
            cp16(sb + OFF_AL + so, Al + goA);                               \
        }                                                                   \
        {                                                                   \
            int row = tid >> 2, cc = tid & 3;                               \
            uint32_t so = (uint32_t)(row * (ROWPAD * 2) + cc * 16);         \
            size_t goB = (size_t)(n0 + row) * K + (k0) + cc * 8;            \
            cp16(sb + OFF_BH + so, Bh + goB);                               \
        }                                                                   \
        asm volatile("cp.async.commit_group;" ::: "memory");                \
    }

    LOAD_STAGE(0, 0)

    for (int s = 0; s < nsteps; s++) {
        if (s + 1 < nsteps) {
            LOAD_STAGE((s + 1) & 1, (s + 1) << 5)
            asm volatile("cp.async.wait_group 1;" ::: "memory");
        } else {
            asm volatile("cp.async.wait_group 0;" ::: "memory");
        }
        __syncthreads();

        uint32_t sb = sbase + (uint32_t)(s & 1) * STAGE_B;
#pragma unroll
        for (int kc = 0; kc < 2; kc++) {
            uint32_t ah[4][4], al[4][4], bh[2][2];
            int arow = wm * 64 + (lane & 7) + ((lane >> 3) & 1) * 8;
            int acol = kc * 16 + ((lane >> 4) & 1) * 8;
#pragma unroll
            for (int mi = 0; mi < 4; mi++) {
                uint32_t ad = sb + (uint32_t)((arow + mi * 16) * (ROWPAD * 2) + acol * 2);
                ldsm4(ah[mi], ad);
                ldsm4(al[mi], ad + OFF_AL);
            }
            int brow = wn * 16 + (lane & 7);
            int bcol = kc * 16 + ((lane >> 3) & 1) * 8;
#pragma unroll
            for (int ni = 0; ni < 2; ni++) {
                uint32_t bd = sb + OFF_BH + (uint32_t)((brow + ni * 8) * (ROWPAD * 2) + bcol * 2);
                ldsm2(bh[ni], bd);
            }
#pragma unroll
            for (int mi = 0; mi < 4; mi++)
#pragma unroll
                for (int ni = 0; ni < 2; ni++) {
                    mma_bf16(acc[mi][ni], ah[mi], bh[ni]);
                    mma_bf16(acc[mi][ni], al[mi], bh[ni]);
                }
        }
        __syncthreads();
    }

    // epilogue: c0,c1 -> row r, cols 2c,2c+1 ; c2,c3 -> row r+8
    int r = lane >> 2, cp = (lane & 3) * 2;
#pragma unroll
    for (int mi = 0; mi < 4; mi++) {
        int mA = m0 + wm * 64 + mi * 16 + r;
        int mB = mA + 8;
#pragma unroll
        for (int ni = 0; ni < 2; ni++) {
            int n = n0 + wn * 16 + ni * 8 + cp;
            float b0v = __ldg(bias + n), b1v = __ldg(bias + n + 1);
            float* a = acc[mi][ni];
            float v00 = fmaxf(a[0] + b0v, 0.f), v01 = fmaxf(a[1] + b1v, 0.f);
            float v10 = fmaxf(a[2] + b0v, 0.f), v11 = fmaxf(a[3] + b1v, 0.f);
            if (Cf) {
                *(float2*)(Cf + (size_t)mA * 1024 + n) = make_float2(v00, v01);
                *(float2*)(Cf + (size_t)mB * 1024 + n) = make_float2(v10, v11);
            } else {
                __nv_bfloat16 h0, l0, h1, l1;
                bf_split(v00, h0, l0); bf_split(v01, h1, l1);
                *(ushort2*)(Ch + (size_t)mA * 1024 + n) =
                    make_ushort2(__bfloat16_as_ushort(h0), __bfloat16_as_ushort(h1));
                *(ushort2*)(Cl + (size_t)mA * 1024 + n) =
                    make_ushort2(__bfloat16_as_ushort(l0), __bfloat16_as_ushort(l1));
                bf_split(v10, h0, l0); bf_split(v11, h1, l1);
                *(ushort2*)(Ch + (size_t)mB * 1024 + n) =
                    make_ushort2(__bfloat16_as_ushort(h0), __bfloat16_as_ushort(h1));
                *(ushort2*)(Cl + (size_t)mB * 1024 + n) =
                    make_ushort2(__bfloat16_as_ushort(l0), __bfloat16_as_ushort(l1));
            }
        }
    }
}

// ---------------- heads ----------------
__global__ __launch_bounds__(128) void k_heads(const float* __restrict__ wc,
                                               const float* __restrict__ bc,
                                               const float* __restrict__ wr,
                                               const float* __restrict__ br) {
    int n = blockIdx.x, tid = threadIdx.x;
    float acc[14];
#pragma unroll
    for (int o = 0; o < 14; o++) acc[o] = 0.0f;
    const float* xr = g_x2 + (size_t)n * HID;
    for (int k = tid; k < HID; k += 128) {
        float xv = xr[k];
        acc[0] = fmaf(xv, wc[k * 2 + 0], acc[0]);
        acc[1] = fmaf(xv, wc[k * 2 + 1], acc[1]);
#pragma unroll
        for (int j = 0; j < 12; j++)
            acc[2 + j] = fmaf(xv, wr[k * 12 + j], acc[2 + j]);
    }
    __shared__ float sh[128];
    for (int o = 0; o < 14; o++) {
        sh[tid] = acc[o]; __syncthreads();
        for (int s = 64; s > 0; s >>= 1) {
            if (tid < s) sh[tid] += sh[tid + s];
            __syncthreads();
        }
        if (tid == 0) {
            float v = sh[0] + (o < 2 ? bc[o] : br[o - 2]);
            if (o < 2) g_logits[n * 2 + o] = v;
            else       g_reg[n * 12 + (o - 2)] = v;
        }
        __syncthreads();
    }
}

// ---------------- losses ----------------
__global__ __launch_bounds__(1024) void k_loss(float* __restrict__ out) {
    int tid = threadIdx.x;
    const float BETA = 1.0f / 9.0f;
    float l0 = g_logits[tid * 2 + 0], l1 = g_logits[tid * 2 + 1];
    int lab = g_labels[tid];
    float mx  = fmaxf(l0, l1);
    float lse = mx + logf(expf(l0 - mx) + expf(l1 - mx));
    float ce  = lse - g_logits[tid * 2 + lab];
    float rl = 0.0f;
    if (lab > 0) {
        const float* pr = g_reg + tid * 12 + lab * 6;
        const float* tg = g_targets + tid * 6;
#pragma unroll
        for (int j = 0; j < 6; j++) {
            float d = fabsf(pr[j] - tg[j]);
            rl += (d < BETA) ? (0.5f * d * d / BETA) : (d - 0.5f * BETA);
        }
    }
    __shared__ float sce[1024];
    __shared__ float srl[1024];
    sce[tid] = ce; srl[tid] = rl;
    __syncthreads();
    for (int s = 512; s > 0; s >>= 1) {
        if (tid < s) { sce[tid] += sce[tid + s]; srl[tid] += srl[tid + s]; }
        __syncthreads();
    }
    if (tid == 0) {
        out[0] = sce[0] / (float)NSAMP;
        out[1] = srl[0] / (float)NSAMP;
    }
}

// ---------------- launch ----------------
extern "C" void kernel_launch(void* const* d_in, const int* in_sizes, int n_in,
                              void* d_out, int out_size) {
    const float* features    = (const float*)d_in[0];
    const float* proposals   = (const float*)d_in[1];
    const float* gt_boxes    = (const float*)d_in[2];
    const int*   gt_labels   = (const int*)  d_in[3];
    const float* gt_ellipses = (const float*)d_in[4];
    const float* w1 = (const float*)d_in[5];
    const float* b1 = (const float*)d_in[6];
    const float* w2 = (const float*)d_in[7];
    const float* b2 = (const float*)d_in[8];
    const float* wc = (const float*)d_in[9];
    const float* bc = (const float*)d_in[10];
    const float* wr = (const float*)d_in[11];
    const float* br = (const float*)d_in[12];
    float* out = (float*)d_out;

    __nv_bfloat16 *pah, *pal, *pw1h, *pw1l, *px1h, *px1l, *pw2h, *pw2l;
    float *px2;
    cudaGetSymbolAddress((void**)&pah,  g_ahi);
    cudaGetSymbolAddress((void**)&pal,  g_alo);
    cudaGetSymbolAddress((void**)&pw1h, g_w1th);
    cudaGetSymbolAddress((void**)&pw1l, g_w1tl);
    cudaGetSymbolAddress((void**)&px1h, g_x1h);
    cudaGetSymbolAddress((void**)&px1l, g_x1l);
    cudaGetSymbolAddress((void**)&pw2h, g_w2th);
    cudaGetSymbolAddress((void**)&pw2l, g_w2tl);
    cudaGetSymbolAddress((void**)&px2,  g_x2);

    const int dyn_bytes = 2 * STAGE_B;   // 51200
    cudaFuncSetAttribute(k_gemm_mma, cudaFuncAttributeMaxDynamicSharedMemorySize, dyn_bytes);

    k_prep<<<dim3(8, 2), 256>>>(proposals, gt_boxes, gt_labels);
    k_sample<<<2, 1024>>>(gt_ellipses);
    k_roi<<<NSAMP, 256>>>(features);
    k_splitT<<<dim3(32, 392), dim3(32, 8)>>>(w1, pw1h, pw1l, DIN);
    k_splitT<<<dim3(32, 32),  dim3(32, 8)>>>(w2, pw2h, pw2l, HID);
    k_gemm_mma<<<dim3(16, 8), 256, dyn_bytes>>>(pah, pal, pw1h, b1,
                                                nullptr, px1h, px1l, DIN);
    k_gemm_mma<<<dim3(16, 8), 256, dyn_bytes>>>(px1h, px1l, pw2h, b2,
                                                px2, nullptr, nullptr, HID);
    k_heads<<<NSAMP, 128>>>(wc, bc, wr, br);
    k_loss<<<1, 1024>>>(out);
}

// round 16
// speedup vs baseline: 2.7248x; 1.1696x over previous
#include <cuda_runtime.h>
#include <cuda_bf16.h>
#include <cstdint>

#define B_IMG   2
#define N_PROP  2000
#define N_GT    16
#define NPROPS  2016
#define C_FEAT  256
#define HF      128
#define WF      128
#define BPI     512
#define NPOS_MAX 128
#define HID     1024
#define DIN     12544
#define NSAMP   1024

// ---------------- device scratch ----------------
__device__ float g_props  [B_IMG * NPROPS * 4];
__device__ int   g_match  [B_IMG * NPROPS];
__device__ int   g_lab    [B_IMG * NPROPS];
__device__ float g_rand   [B_IMG * NPROPS];
__device__ float g_boxes  [NSAMP * 4];
__device__ int   g_labels [NSAMP];
__device__ float g_targets[NSAMP * 6];
__device__ __align__(16) __nv_bfloat16 g_ahi [NSAMP * DIN];
__device__ __align__(16) __nv_bfloat16 g_w1th[HID * DIN];
__device__ __align__(16) __nv_bfloat16 g_x1h [NSAMP * HID];
__device__ __align__(16) __nv_bfloat16 g_w2th[HID * HID];
__device__ __align__(16) float g_x2[NSAMP * HID];
__device__ float g_logits [NSAMP * 2];
__device__ float g_reg    [NSAMP * 12];

// ---------------- helpers ----------------
__device__ __forceinline__ uint32_t smem_u32(const void* p) {
    uint32_t a;
    asm("{ .reg .u64 t; cvta.to.shared.u64 t, %1; cvt.u32.u64 %0, t; }" : "=r"(a) : "l"(p));
    return a;
}
__device__ __forceinline__ void cp16(uint32_t saddr, const void* g) {
    asm volatile("cp.async.cg.shared.global [%0], [%1], 16;" :: "r"(saddr), "l"(g));
}
__device__ __forceinline__ void ldsm4(uint32_t* r, uint32_t a) {
    asm volatile("ldmatrix.sync.aligned.m8n8.x4.shared.b16 {%0,%1,%2,%3}, [%4];"
                 : "=r"(r[0]), "=r"(r[1]), "=r"(r[2]), "=r"(r[3]) : "r"(a));
}
__device__ __forceinline__ void ldsm2(uint32_t* r, uint32_t a) {
    asm volatile("ldmatrix.sync.aligned.m8n8.x2.shared.b16 {%0,%1}, [%2];"
                 : "=r"(r[0]), "=r"(r[1]) : "r"(a));
}
__device__ __forceinline__ void mma_bf16(float* d, const uint32_t* a, const uint32_t* b) {
    asm volatile("mma.sync.aligned.m16n8k16.row.col.f32.bf16.bf16.f32 "
                 "{%0,%1,%2,%3},{%4,%5,%6,%7},{%8,%9},{%0,%1,%2,%3};"
                 : "+f"(d[0]), "+f"(d[1]), "+f"(d[2]), "+f"(d[3])
                 : "r"(a[0]), "r"(a[1]), "r"(a[2]), "r"(a[3]), "r"(b[0]), "r"(b[1]));
}

// ---------------- threefry2x32, key=(0,42), partitionable ----------------
__device__ __forceinline__ uint32_t rotl32(uint32_t x, int r) { return (x << r) | (x >> (32 - r)); }
__device__ __forceinline__ void threefry_0_42(uint32_t c0, uint32_t c1, uint32_t& o0, uint32_t& o1) {
    const uint32_t k0 = 0u, k1 = 42u, k2 = 0x1BD11BDAu ^ 42u;
    uint32_t x0 = c0 + k0, x1 = c1 + k1;
#define TFR(r) { x0 += x1; x1 = rotl32(x1, r); x1 ^= x0; }
    TFR(13) TFR(15) TFR(26) TFR(6)   x0 += k1; x1 += k2 + 1u;
    TFR(17) TFR(29) TFR(16) TFR(24)  x0 += k2; x1 += k0 + 2u;
    TFR(13) TFR(15) TFR(26) TFR(6)   x0 += k0; x1 += k1 + 3u;
    TFR(17) TFR(29) TFR(16) TFR(24)  x0 += k1; x1 += k2 + 4u;
    TFR(13) TFR(15) TFR(26) TFR(6)   x0 += k2; x1 += k0 + 5u;
#undef TFR
    o0 = x0; o1 = x1;
}

// ---------------- kernel 1: props + IoU + label + rand ----------------
__global__ void k_prep(const float* __restrict__ proposals,
                       const float* __restrict__ gt_boxes,
                       const int*   __restrict__ gt_labels) {
    int b = blockIdx.y;
    int p = blockIdx.x * blockDim.x + threadIdx.x;
    __shared__ float sg[N_GT * 4];
    __shared__ float sga[N_GT];
    __shared__ int   sgl[N_GT];
    if (threadIdx.x < N_GT) {
        int g = threadIdx.x;
        float gx1 = gt_boxes[(b * N_GT + g) * 4 + 0];
        float gy1 = gt_boxes[(b * N_GT + g) * 4 + 1];
        float gx2 = gt_boxes[(b * N_GT + g) * 4 + 2];
        float gy2 = gt_boxes[(b * N_GT + g) * 4 + 3];
        sg[g * 4 + 0] = gx1; sg[g * 4 + 1] = gy1;
        sg[g * 4 + 2] = gx2; sg[g * 4 + 3] = gy2;
        sga[g] = (gx2 - gx1) * (gy2 - gy1);
        sgl[g] = gt_labels[b * N_GT + g];
    }
    __syncthreads();
    if (p >= NPROPS) return;
    float px1, py1, px2, py2;
    if (p < N_PROP) {
        const float* pp = proposals + (size_t)(b * N_PROP + p) * 4;
        px1 = pp[0]; py1 = pp[1]; px2 = pp[2]; py2 = pp[3];
    } else {
        int g = p - N_PROP;
        px1 = sg[g * 4 + 0]; py1 = sg[g * 4 + 1];
        px2 = sg[g * 4 + 2]; py2 = sg[g * 4 + 3];
    }
    int n = b * NPROPS + p;
    g_props[n * 4 + 0] = px1; g_props[n * 4 + 1] = py1;
    g_props[n * 4 + 2] = px2; g_props[n * 4 + 3] = py2;
    float ap = (px2 - px1) * (py2 - py1);
    float best = -1.0f; int bi = 0;
#pragma unroll
    for (int g = 0; g < N_GT; g++) {
        float ltx = fmaxf(sg[g * 4 + 0], px1);
        float lty = fmaxf(sg[g * 4 + 1], py1);
        float rbx = fminf(sg[g * 4 + 2], px2);
        float rby = fminf(sg[g * 4 + 3], py2);
        float w = fmaxf(rbx - ltx, 0.0f);
        float h = fmaxf(rby - lty, 0.0f);
        float inter = w * h;
        float iou = inter / (sga[g] + ap - inter);
        if (iou > best) { best = iou; bi = g; }
    }
    g_match[n] = bi;
    g_lab[n]   = (best < 0.5f) ? 0 : sgl[bi];
    uint32_t o0, o1;
    threefry_0_42(0u, (uint32_t)n, o0, o1);
    uint32_t bits = o0 ^ o1;
    g_rand[n] = __uint_as_float((bits >> 9) | 0x3f800000u) - 1.0f;
}

// ---------------- kernel 2: sampling ----------------
__device__ __forceinline__ unsigned long long pack_key(float f, int i) {
    uint32_t u = __float_as_uint(f);
    u = (u & 0x80000000u) ? ~u : (u | 0x80000000u);
    return ((unsigned long long)u << 32) | (uint32_t)(0x7FF - i);
}
__device__ void bitonic_desc(unsigned long long* keys, int tid) {
    for (int k = 2; k <= 2048; k <<= 1)
        for (int j = k >> 1; j > 0; j >>= 1) {
            __syncthreads();
            for (int t = tid; t < 2048; t += 1024) {
                int ixj = t ^ j;
                if (ixj > t) {
                    unsigned long long a = keys[t], c = keys[ixj];
                    bool descBlk = ((t & k) == 0);
                    if (descBlk ? (a < c) : (a > c)) { keys[t] = c; keys[ixj] = a; }
                }
            }
        }
    __syncthreads();
}
__global__ __launch_bounds__(1024) void k_sample(const float* __restrict__ gt_ellipses) {
    int b = blockIdx.x, tid = threadIdx.x;
    __shared__ unsigned long long keys[2048];
    __shared__ unsigned char cap[2048];
    for (int i = tid; i < 2048; i += 1024) {
        cap[i] = 0;
        unsigned long long kv = 0ull;
        if (i < NPROPS) {
            float r = g_rand[b * NPROPS + i];
            float s = (g_lab[b * NPROPS + i] > 0) ? r : -1e9f;
            kv = pack_key(s, i);
        }
        keys[i] = kv;
    }
    __syncthreads();
    bitonic_desc(keys, tid);
    if (tid < NPOS_MAX) {
        unsigned long long kv = keys[tid];
        if (kv) {
            int i = 0x7FF - (int)(uint32_t)(kv & 0xFFFFFFFFull);
            if (i >= 0 && i < NPROPS && g_lab[b * NPROPS + i] > 0) cap[i] = 1;
        }
    }
    __syncthreads();
    for (int i = tid; i < 2048; i += 1024) {
        unsigned long long kv = 0ull;
        if (i < NPROPS) {
            float r = g_rand[b * NPROPS + i];
            float prio = cap[i] ? (r + 2.0f)
                                : ((g_lab[b * NPROPS + i] == 0) ? r : -1e9f);
            kv = pack_key(prio, i);
        }
        keys[i] = kv;
    }
    __syncthreads();
    bitonic_desc(keys, tid);
    if (tid < BPI) {
        int i   = 0x7FF - (int)(uint32_t)(keys[tid] & 0xFFFFFFFFull);
        int n   = b * BPI + tid;
        int src = b * NPROPS + i;
        float x1 = g_props[src * 4 + 0], y1 = g_props[src * 4 + 1];
        float x2 = g_props[src * 4 + 2], y2 = g_props[src * 4 + 3];
        g_boxes[n * 4 + 0] = x1; g_boxes[n * 4 + 1] = y1;
        g_boxes[n * 4 + 2] = x2; g_boxes[n * 4 + 3] = y2;
        int lab = g_lab[src];
        g_labels[n] = lab;
        int m = g_match[src];
        const float* el = gt_ellipses + (size_t)(b * N_GT + m) * 5;
        float ea = el[0], eb = el[1], ex = el[2], ey = el[3], th = el[4];
        float w  = fmaxf(x2 - x1, 1.0f), h = fmaxf(y2 - y1, 1.0f);
        float cx = 0.5f * (x1 + x2),    cy = 0.5f * (y1 + y2);
        g_targets[n * 6 + 0] = (ex - cx) / w;
        g_targets[n * 6 + 1] = (ey - cy) / h;
        g_targets[n * 6 + 2] = logf(fmaxf(2.0f * ea, 0.001f) / w);
        g_targets[n * 6 + 3] = logf(fmaxf(2.0f * eb, 0.001f) / h);
        g_targets[n * 6 + 4] = sinf(2.0f * th);
        g_targets[n * 6 + 5] = cosf(2.0f * th);
    }
}

// ---------------- kernel 3: RoI-align -> bf16 ----------------
__global__ __launch_bounds__(256) void k_roi(const float* __restrict__ features) {
    int n   = blockIdx.x;
    int b   = n >> 9;
    int tid = threadIdx.x;
    __shared__ int   sy0[14], sx0[14];
    __shared__ float sly[14], slx[14];
    if (tid < 28) {
        float bx1 = g_boxes[n * 4 + 0] * 0.125f;
        float by1 = g_boxes[n * 4 + 1] * 0.125f;
        float bx2 = g_boxes[n * 4 + 2] * 0.125f;
        float by2 = g_boxes[n * 4 + 3] * 0.125f;
        float bw = fmaxf(bx2 - bx1, 1.0f) / 7.0f;
        float bh = fmaxf(by2 - by1, 1.0f) / 7.0f;
        if (tid < 14) {
            float off = ((float)tid + 0.5f) / 2.0f;
            float ys = fminf(fmaxf(by1 + off * bh, 0.0f), 127.0f);
            int y0 = (int)floorf(ys); y0 = min(max(y0, 0), 126);
            sy0[tid] = y0; sly[tid] = ys - (float)y0;
        } else {
            int i = tid - 14;
            float off = ((float)i + 0.5f) / 2.0f;
            float xs = fminf(fmaxf(bx1 + off * bw, 0.0f), 127.0f);
            int x0 = (int)floorf(xs); x0 = min(max(x0, 0), 126);
            sx0[i] = x0; slx[i] = xs - (float)x0;
        }
    }
    __syncthreads();
    const float* fb = features + (size_t)b * C_FEAT * HF * WF;
    for (int it = 0; it < 49; it++) {
        int e = it * 256 + tid;
        int c = e / 49;
        int r = e - c * 49;
        int py = r / 7, px = r - py * 7;
        const float* fc = fb + (size_t)c * (HF * WF);
        float acc = 0.0f;
#pragma unroll
        for (int sy = 0; sy < 2; sy++) {
            int i = py * 2 + sy;
            int y0 = sy0[i]; float fy = sly[i];
            const float* rowp = fc + y0 * WF;
#pragma unroll
            for (int sx = 0; sx < 2; sx++) {
                int j = px * 2 + sx;
                int x0 = sx0[j]; float fx = slx[j];
                float v00 = __ldg(rowp + x0);
                float v01 = __ldg(rowp + x0 + 1);
                float v10 = __ldg(rowp + WF + x0);
                float v11 = __ldg(rowp + WF + x0 + 1);
                float top = v00 + (v01 - v00) * fx;
                float bot = v10 + (v11 - v10) * fx;
                acc += top + (bot - top) * fy;
            }
        }
        g_ahi[(size_t)n * DIN + e] = __float2bfloat16_rn(acc * 0.25f);
    }
}

// ---------------- transpose weights to bf16: out[n][k] = bf16(in[k][n]) ----------------
__global__ void k_splitT(const float* __restrict__ in,
                         __nv_bfloat16* __restrict__ oh, int K) {
    __shared__ float t[32][33];
    int nb = blockIdx.x * 32, kb = blockIdx.y * 32;
    int tx = threadIdx.x, ty = threadIdx.y;
#pragma unroll
    for (int r = 0; r < 4; r++)
        t[ty + r * 8][tx] = in[(size_t)(kb + ty + r * 8) * HID + nb + tx];
    __syncthreads();
#pragma unroll
    for (int r = 0; r < 4; r++) {
        int n = nb + ty + r * 8;
        oh[(size_t)n * K + kb + tx] = __float2bfloat16_rn(t[tx][ty + r * 8]);
    }
}

// ---------------- HMMA bf16 GEMM + bias + ReLU (single-term) ----------------
// C = relu(A @ B^T + bias); A[M][K], B[N][K] bf16 (calibrated error model:
// dropped-residual per-element ~2.5e-3 rms -> ~1.3e-4 on final loss scalars).
// CTA 128(M) x 64(N), 8 warps (2x4), warp tile 64x16, BK=32, 2-stage cp.async.
// grid = (16, 8) -> 128 CTAs (one wave on 148 SMs).
#define ROWPAD 40                     // bf16 per smem row (80 B, conflict-free ldmatrix)
#define TILE_AB (128 * ROWPAD * 2)    // 10240 B (A)
#define TILE_BB (64 * ROWPAD * 2)     // 5120 B  (B)
#define OFF_BH  TILE_AB
#define STAGE_B (TILE_AB + TILE_BB)   // 15360 B
__global__ __launch_bounds__(256, 1) void k_gemm_mma(
    const __nv_bfloat16* __restrict__ Ah,
    const __nv_bfloat16* __restrict__ Bh,
    const float* __restrict__ bias,
    float* __restrict__ Cf, __nv_bfloat16* __restrict__ Ch,
    int K)
{
    extern __shared__ char sm[];
    uint32_t sbase = smem_u32(sm);
    int tid = threadIdx.x, wid = tid >> 5, lane = tid & 31;
    int wm = wid >> 2, wn = wid & 3;              // 2 x 4 warp grid
    int m0 = blockIdx.y << 7, n0 = blockIdx.x << 6;

    float acc[4][2][4];
#pragma unroll
    for (int i = 0; i < 4; i++)
#pragma unroll
        for (int j = 0; j < 2; j++)
#pragma unroll
            for (int q = 0; q < 4; q++) acc[i][j][q] = 0.0f;

    int nsteps = K >> 5;

    // per stage: A = 512 16B-chunks (2/thread); B = 256 (1/thread)
#define LOAD_STAGE(st, k0)                                                  \
    {                                                                       \
        uint32_t sb = sbase + (uint32_t)(st) * STAGE_B;                     \
        _Pragma("unroll")                                                   \
        for (int i = 0; i < 2; i++) {                                       \
            int c   = tid + (i << 8);                                       \
            int row = c >> 2, cc = c & 3;                                   \
            uint32_t so = (uint32_t)(row * (ROWPAD * 2) + cc * 16);         \
            size_t goA = (size_t)(m0 + row) * K + (k0) + cc * 8;            \
            cp16(sb + so, Ah + goA);                                        \
        }                                                                   \
        {                                                                   \
            int row = tid >> 2, cc = tid & 3;                               \
            uint32_t so = (uint32_t)(row * (ROWPAD * 2) + cc * 16);         \
            size_t goB = (size_t)(n0 + row) * K + (k0) + cc * 8;            \
            cp16(sb + OFF_BH + so, Bh + goB);                               \
        }                                                                   \
        asm volatile("cp.async.commit_group;" ::: "memory");                \
    }

    LOAD_STAGE(0, 0)

    for (int s = 0; s < nsteps; s++) {
        if (s + 1 < nsteps) {
            LOAD_STAGE((s + 1) & 1, (s + 1) << 5)
            asm volatile("cp.async.wait_group 1;" ::: "memory");
        } else {
            asm volatile("cp.async.wait_group 0;" ::: "memory");
        }
        __syncthreads();

        uint32_t sb = sbase + (uint32_t)(s & 1) * STAGE_B;
#pragma unroll
        for (int kc = 0; kc < 2; kc++) {
            uint32_t ah[4][4], bh[2][2];
            int arow = wm * 64 + (lane & 7) + ((lane >> 3) & 1) * 8;
            int acol = kc * 16 + ((lane >> 4) & 1) * 8;
#pragma unroll
            for (int mi = 0; mi < 4; mi++) {
                uint32_t ad = sb + (uint32_t)((arow + mi * 16) * (ROWPAD * 2) + acol * 2);
                ldsm4(ah[mi], ad);
            }
            int brow = wn * 16 + (lane & 7);
            int bcol = kc * 16 + ((lane >> 3) & 1) * 8;
#pragma unroll
            for (int ni = 0; ni < 2; ni++) {
                uint32_t bd = sb + OFF_BH + (uint32_t)((brow + ni * 8) * (ROWPAD * 2) + bcol * 2);
                ldsm2(bh[ni], bd);
            }
#pragma unroll
            for (int mi = 0; mi < 4; mi++)
#pragma unroll
                for (int ni = 0; ni < 2; ni++)
                    mma_bf16(acc[mi][ni], ah[mi], bh[ni]);
        }
        __syncthreads();
    }

    // epilogue: c0,c1 -> row r, cols 2c,2c+1 ; c2,c3 -> row r+8
    int r = lane >> 2, cp = (lane & 3) * 2;
#pragma unroll
    for (int mi = 0; mi < 4; mi++) {
        int mA = m0 + wm * 64 + mi * 16 + r;
        int mB = mA + 8;
#pragma unroll
        for (int ni = 0; ni < 2; ni++) {
            int n = n0 + wn * 16 + ni * 8 + cp;
            float b0v = __ldg(bias + n), b1v = __ldg(bias + n + 1);
            float* a = acc[mi][ni];
            float v00 = fmaxf(a[0] + b0v, 0.f), v01 = fmaxf(a[1] + b1v, 0.f);
            float v10 = fmaxf(a[2] + b0v, 0.f), v11 = fmaxf(a[3] + b1v, 0.f);
            if (Cf) {
                *(float2*)(Cf + (size_t)mA * 1024 + n) = make_float2(v00, v01);
                *(float2*)(Cf + (size_t)mB * 1024 + n) = make_float2(v10, v11);
            } else {
                *(ushort2*)(Ch + (size_t)mA * 1024 + n) =
                    make_ushort2(__bfloat16_as_ushort(__float2bfloat16_rn(v00)),
                                 __bfloat16_as_ushort(__float2bfloat16_rn(v01)));
                *(ushort2*)(Ch + (size_t)mB * 1024 + n) =
                    make_ushort2(__bfloat16_as_ushort(__float2bfloat16_rn(v10)),
                                 __bfloat16_as_ushort(__float2bfloat16_rn(v11)));
            }
        }
    }
}

// ---------------- heads ----------------
__global__ __launch_bounds__(128) void k_heads(const float* __restrict__ wc,
                                               const float* __restrict__ bc,
                                               const float* __restrict__ wr,
                                               const float* __restrict__ br) {
    int n = blockIdx.x, tid = threadIdx.x;
    float acc[14];
#pragma unroll
    for (int o = 0; o < 14; o++) acc[o] = 0.0f;
    const float* xr = g_x2 + (size_t)n * HID;
    for (int k = tid; k < HID; k += 128) {
        float xv = xr[k];
        acc[0] = fmaf(xv, wc[k * 2 + 0], acc[0]);
        acc[1] = fmaf(xv, wc[k * 2 + 1], acc[1]);
#pragma unroll
        for (int j = 0; j < 12; j++)
            acc[2 + j] = fmaf(xv, wr[k * 12 + j], acc[2 + j]);
    }
    __shared__ float sh[128];
    for (int o = 0; o < 14; o++) {
        sh[tid] = acc[o]; __syncthreads();
        for (int s = 64; s > 0; s >>= 1) {
            if (tid < s) sh[tid] += sh[tid + s];
            __syncthreads();
        }
        if (tid == 0) {
            float v = sh[0] + (o < 2 ? bc[o] : br[o - 2]);
            if (o < 2) g_logits[n * 2 + o] = v;
            else       g_reg[n * 12 + (o - 2)] = v;
        }
        __syncthreads();
    }
}

// ---------------- losses ----------------
__global__ __launch_bounds__(1024) void k_loss(float* __restrict__ out) {
    int tid = threadIdx.x;
    const float BETA = 1.0f / 9.0f;
    float l0 = g_logits[tid * 2 + 0], l1 = g_logits[tid * 2 + 1];
    int lab = g_labels[tid];
    float mx  = fmaxf(l0, l1);
    float lse = mx + logf(expf(l0 - mx) + expf(l1 - mx));
    float ce  = lse - g_logits[tid * 2 + lab];
    float rl = 0.0f;
    if (lab > 0) {
        const float* pr = g_reg + tid * 12 + lab * 6;
        const float* tg = g_targets + tid * 6;
#pragma unroll
        for (int j = 0; j < 6; j++) {
            float d = fabsf(pr[j] - tg[j]);
            rl += (d < BETA) ? (0.5f * d * d / BETA) : (d - 0.5f * BETA);
        }
    }
    __shared__ float sce[1024];
    __shared__ float srl[1024];
    sce[tid] = ce; srl[tid] = rl;
    __syncthreads();
    for (int s = 512; s > 0; s >>= 1) {
        if (tid < s) { sce[tid] += sce[tid + s]; srl[tid] += srl[tid + s]; }
        __syncthreads();
    }
    if (tid == 0) {
        out[0] = sce[0] / (float)NSAMP;
        out[1] = srl[0] / (float)NSAMP;
    }
}

// ---------------- launch ----------------
extern "C" void kernel_launch(void* const* d_in, const int* in_sizes, int n_in,
                              void* d_out, int out_size) {
    const float* features    = (const float*)d_in[0];
    const float* proposals   = (const float*)d_in[1];
    const float* gt_boxes    = (const float*)d_in[2];
    const int*   gt_labels   = (const int*)  d_in[3];
    const float* gt_ellipses = (const float*)d_in[4];
    const float* w1 = (const float*)d_in[5];
    const float* b1 = (const float*)d_in[6];
    const float* w2 = (const float*)d_in[7];
    const float* b2 = (const float*)d_in[8];
    const float* wc = (const float*)d_in[9];
    const float* bc = (const float*)d_in[10];
    const float* wr = (const float*)d_in[11];
    const float* br = (const float*)d_in[12];
    float* out = (float*)d_out;

    __nv_bfloat16 *pah, *pw1h, *px1h, *pw2h;
    float *px2;
    cudaGetSymbolAddress((void**)&pah,  g_ahi);
    cudaGetSymbolAddress((void**)&pw1h, g_w1th);
    cudaGetSymbolAddress((void**)&px1h, g_x1h);
    cudaGetSymbolAddress((void**)&pw2h, g_w2th);
    cudaGetSymbolAddress((void**)&px2,  g_x2);

    const int dyn_bytes = 2 * STAGE_B;   // 30720
    cudaFuncSetAttribute(k_gemm_mma, cudaFuncAttributeMaxDynamicSharedMemorySize, dyn_bytes);

    k_prep<<<dim3(8, 2), 256>>>(proposals, gt_boxes, gt_labels);
    k_sample<<<2, 1024>>>(gt_ellipses);
    k_roi<<<NSAMP, 256>>>(features);
    k_splitT<<<dim3(32, 392), dim3(32, 8)>>>(w1, pw1h, DIN);
    k_splitT<<<dim3(32, 32),  dim3(32, 8)>>>(w2, pw2h, HID);
    k_gemm_mma<<<dim3(16, 8), 256, dyn_bytes>>>(pah,  pw1h, b1, nullptr, px1h, DIN);
    k_gemm_mma<<<dim3(16, 8), 256, dyn_bytes>>>(px1h, pw2h, b2, px2, nullptr, HID);
    k_heads<<<NSAMP, 128>>>(wc, bc, wr, br);
    k_loss<<<1, 1024>>>(out);
}

// round 17
// speedup vs baseline: 2.9899x; 1.0973x over previous
#include <cuda_runtime.h>
#include <cuda_bf16.h>
#include <cstdint>

#define B_IMG   2
#define N_PROP  2000
#define N_GT    16
#define NPROPS  2016
#define C_FEAT  256
#define HF      128
#define WF      128
#define BPI     512
#define NPOS_MAX 128
#define HID     1024
#define DIN     12544
#define NSAMP   1024

// ---------------- device scratch ----------------
__device__ float g_props  [B_IMG * NPROPS * 4];
__device__ int   g_match  [B_IMG * NPROPS];
__device__ int   g_lab    [B_IMG * NPROPS];
__device__ float g_rand   [B_IMG * NPROPS];
__device__ float g_boxes  [NSAMP * 4];
__device__ int   g_labels [NSAMP];
__device__ float g_targets[NSAMP * 6];
__device__ __align__(16) __nv_bfloat16 g_ahi [NSAMP * DIN];
__device__ __align__(16) __nv_bfloat16 g_w1th[HID * DIN];
__device__ __align__(16) __nv_bfloat16 g_x1h [NSAMP * HID];
__device__ __align__(16) __nv_bfloat16 g_w2th[HID * HID];
__device__ __align__(16) float g_x2[NSAMP * HID];
__device__ float g_logits [NSAMP * 2];
__device__ float g_reg    [NSAMP * 12];

// ---------------- helpers ----------------
__device__ __forceinline__ uint32_t smem_u32(const void* p) {
    uint32_t a;
    asm("{ .reg .u64 t; cvta.to.shared.u64 t, %1; cvt.u32.u64 %0, t; }" : "=r"(a) : "l"(p));
    return a;
}
__device__ __forceinline__ void cp16(uint32_t saddr, const void* g) {
    asm volatile("cp.async.cg.shared.global [%0], [%1], 16;" :: "r"(saddr), "l"(g));
}
__device__ __forceinline__ void ldsm4(uint32_t* r, uint32_t a) {
    asm volatile("ldmatrix.sync.aligned.m8n8.x4.shared.b16 {%0,%1,%2,%3}, [%4];"
                 : "=r"(r[0]), "=r"(r[1]), "=r"(r[2]), "=r"(r[3]) : "r"(a));
}
__device__ __forceinline__ void ldsm2(uint32_t* r, uint32_t a) {
    asm volatile("ldmatrix.sync.aligned.m8n8.x2.shared.b16 {%0,%1}, [%2];"
                 : "=r"(r[0]), "=r"(r[1]) : "r"(a));
}
__device__ __forceinline__ void mma_bf16(float* d, const uint32_t* a, const uint32_t* b) {
    asm volatile("mma.sync.aligned.m16n8k16.row.col.f32.bf16.bf16.f32 "
                 "{%0,%1,%2,%3},{%4,%5,%6,%7},{%8,%9},{%0,%1,%2,%3};"
                 : "+f"(d[0]), "+f"(d[1]), "+f"(d[2]), "+f"(d[3])
                 : "r"(a[0]), "r"(a[1]), "r"(a[2]), "r"(a[3]), "r"(b[0]), "r"(b[1]));
}

// ---------------- threefry2x32, key=(0,42), partitionable ----------------
__device__ __forceinline__ uint32_t rotl32(uint32_t x, int r) { return (x << r) | (x >> (32 - r)); }
__device__ __forceinline__ void threefry_0_42(uint32_t c0, uint32_t c1, uint32_t& o0, uint32_t& o1) {
    const uint32_t k0 = 0u, k1 = 42u, k2 = 0x1BD11BDAu ^ 42u;
    uint32_t x0 = c0 + k0, x1 = c1 + k1;
#define TFR(r) { x0 += x1; x1 = rotl32(x1, r); x1 ^= x0; }
    TFR(13) TFR(15) TFR(26) TFR(6)   x0 += k1; x1 += k2 + 1u;
    TFR(17) TFR(29) TFR(16) TFR(24)  x0 += k2; x1 += k0 + 2u;
    TFR(13) TFR(15) TFR(26) TFR(6)   x0 += k0; x1 += k1 + 3u;
    TFR(17) TFR(29) TFR(16) TFR(24)  x0 += k1; x1 += k2 + 4u;
    TFR(13) TFR(15) TFR(26) TFR(6)   x0 += k2; x1 += k0 + 5u;
#undef TFR
    o0 = x0; o1 = x1;
}

// ---------------- kernel 1: props + IoU + label + rand ----------------
__global__ void k_prep(const float* __restrict__ proposals,
                       const float* __restrict__ gt_boxes,
                       const int*   __restrict__ gt_labels) {
    int b = blockIdx.y;
    int p = blockIdx.x * blockDim.x + threadIdx.x;
    __shared__ float sg[N_GT * 4];
    __shared__ float sga[N_GT];
    __shared__ int   sgl[N_GT];
    if (threadIdx.x < N_GT) {
        int g = threadIdx.x;
        float gx1 = gt_boxes[(b * N_GT + g) * 4 + 0];
        float gy1 = gt_boxes[(b * N_GT + g) * 4 + 1];
        float gx2 = gt_boxes[(b * N_GT + g) * 4 + 2];
        float gy2 = gt_boxes[(b * N_GT + g) * 4 + 3];
        sg[g * 4 + 0] = gx1; sg[g * 4 + 1] = gy1;
        sg[g * 4 + 2] = gx2; sg[g * 4 + 3] = gy2;
        sga[g] = (gx2 - gx1) * (gy2 - gy1);
        sgl[g] = gt_labels[b * N_GT + g];
    }
    __syncthreads();
    if (p >= NPROPS) return;
    float px1, py1, px2, py2;
    if (p < N_PROP) {
        const float* pp = proposals + (size_t)(b * N_PROP + p) * 4;
        px1 = pp[0]; py1 = pp[1]; px2 = pp[2]; py2 = pp[3];
    } else {
        int g = p - N_PROP;
        px1 = sg[g * 4 + 0]; py1 = sg[g * 4 + 1];
        px2 = sg[g * 4 + 2]; py2 = sg[g * 4 + 3];
    }
    int n = b * NPROPS + p;
    g_props[n * 4 + 0] = px1; g_props[n * 4 + 1] = py1;
    g_props[n * 4 + 2] = px2; g_props[n * 4 + 3] = py2;
    float ap = (px2 - px1) * (py2 - py1);
    float best = -1.0f; int bi = 0;
#pragma unroll
    for (int g = 0; g < N_GT; g++) {
        float ltx = fmaxf(sg[g * 4 + 0], px1);
        float lty = fmaxf(sg[g * 4 + 1], py1);
        float rbx = fminf(sg[g * 4 + 2], px2);
        float rby = fminf(sg[g * 4 + 3], py2);
        float w = fmaxf(rbx - ltx, 0.0f);
        float h = fmaxf(rby - lty, 0.0f);
        float inter = w * h;
        float iou = inter / (sga[g] + ap - inter);
        if (iou > best) { best = iou; bi = g; }
    }
    g_match[n] = bi;
    g_lab[n]   = (best < 0.5f) ? 0 : sgl[bi];
    uint32_t o0, o1;
    threefry_0_42(0u, (uint32_t)n, o0, o1);
    uint32_t bits = o0 ^ o1;
    g_rand[n] = __uint_as_float((bits >> 9) | 0x3f800000u) - 1.0f;
}

// ---------------- kernel 2: sampling ----------------
__device__ __forceinline__ unsigned long long pack_key(float f, int i) {
    uint32_t u = __float_as_uint(f);
    u = (u & 0x80000000u) ? ~u : (u | 0x80000000u);
    return ((unsigned long long)u << 32) | (uint32_t)(0x7FF - i);
}
__device__ void bitonic_desc(unsigned long long* keys, int tid) {
    for (int k = 2; k <= 2048; k <<= 1)
        for (int j = k >> 1; j > 0; j >>= 1) {
            __syncthreads();
            for (int t = tid; t < 2048; t += 1024) {
                int ixj = t ^ j;
                if (ixj > t) {
                    unsigned long long a = keys[t], c = keys[ixj];
                    bool descBlk = ((t & k) == 0);
                    if (descBlk ? (a < c) : (a > c)) { keys[t] = c; keys[ixj] = a; }
                }
            }
        }
    __syncthreads();
}
__global__ __launch_bounds__(1024) void k_sample(const float* __restrict__ gt_ellipses) {
    int b = blockIdx.x, tid = threadIdx.x;
    __shared__ unsigned long long keys[2048];
    __shared__ unsigned char cap[2048];
    for (int i = tid; i < 2048; i += 1024) {
        cap[i] = 0;
        unsigned long long kv = 0ull;
        if (i < NPROPS) {
            float r = g_rand[b * NPROPS + i];
            float s = (g_lab[b * NPROPS + i] > 0) ? r : -1e9f;
            kv = pack_key(s, i);
        }
        keys[i] = kv;
    }
    __syncthreads();
    bitonic_desc(keys, tid);
    if (tid < NPOS_MAX) {
        unsigned long long kv = keys[tid];
        if (kv) {
            int i = 0x7FF - (int)(uint32_t)(kv & 0xFFFFFFFFull);
            if (i >= 0 && i < NPROPS && g_lab[b * NPROPS + i] > 0) cap[i] = 1;
        }
    }
    __syncthreads();
    for (int i = tid; i < 2048; i += 1024) {
        unsigned long long kv = 0ull;
        if (i < NPROPS) {
            float r = g_rand[b * NPROPS + i];
            float prio = cap[i] ? (r + 2.0f)
                                : ((g_lab[b * NPROPS + i] == 0) ? r : -1e9f);
            kv = pack_key(prio, i);
        }
        keys[i] = kv;
    }
    __syncthreads();
    bitonic_desc(keys, tid);
    if (tid < BPI) {
        int i   = 0x7FF - (int)(uint32_t)(keys[tid] & 0xFFFFFFFFull);
        int n   = b * BPI + tid;
        int src = b * NPROPS + i;
        float x1 = g_props[src * 4 + 0], y1 = g_props[src * 4 + 1];
        float x2 = g_props[src * 4 + 2], y2 = g_props[src * 4 + 3];
        g_boxes[n * 4 + 0] = x1; g_boxes[n * 4 + 1] = y1;
        g_boxes[n * 4 + 2] = x2; g_boxes[n * 4 + 3] = y2;
        int lab = g_lab[src];
        g_labels[n] = lab;
        int m = g_match[src];
        const float* el = gt_ellipses + (size_t)(b * N_GT + m) * 5;
        float ea = el[0], eb = el[1], ex = el[2], ey = el[3], th = el[4];
        float w  = fmaxf(x2 - x1, 1.0f), h = fmaxf(y2 - y1, 1.0f);
        float cx = 0.5f * (x1 + x2),    cy = 0.5f * (y1 + y2);
        g_targets[n * 6 + 0] = (ex - cx) / w;
        g_targets[n * 6 + 1] = (ey - cy) / h;
        g_targets[n * 6 + 2] = logf(fmaxf(2.0f * ea, 0.001f) / w);
        g_targets[n * 6 + 3] = logf(fmaxf(2.0f * eb, 0.001f) / h);
        g_targets[n * 6 + 4] = sinf(2.0f * th);
        g_targets[n * 6 + 5] = cosf(2.0f * th);
    }
}

// ---------------- kernel 3: RoI-align -> bf16 ----------------
__global__ __launch_bounds__(256) void k_roi(const float* __restrict__ features) {
    int n   = blockIdx.x;
    int b   = n >> 9;
    int tid = threadIdx.x;
    __shared__ int   sy0[14], sx0[14];
    __shared__ float sly[14], slx[14];
    if (tid < 28) {
        float bx1 = g_boxes[n * 4 + 0] * 0.125f;
        float by1 = g_boxes[n * 4 + 1] * 0.125f;
        float bx2 = g_boxes[n * 4 + 2] * 0.125f;
        float by2 = g_boxes[n * 4 + 3] * 0.125f;
        float bw = fmaxf(bx2 - bx1, 1.0f) / 7.0f;
        float bh = fmaxf(by2 - by1, 1.0f) / 7.0f;
        if (tid < 14) {
            float off = ((float)tid + 0.5f) / 2.0f;
            float ys = fminf(fmaxf(by1 + off * bh, 0.0f), 127.0f);
            int y0 = (int)floorf(ys); y0 = min(max(y0, 0), 126);
            sy0[tid] = y0; sly[tid] = ys - (float)y0;
        } else {
            int i = tid - 14;
            float off = ((float)i + 0.5f) / 2.0f;
            float xs = fminf(fmaxf(bx1 + off * bw, 0.0f), 127.0f);
            int x0 = (int)floorf(xs); x0 = min(max(x0, 0), 126);
            sx0[i] = x0; slx[i] = xs - (float)x0;
        }
    }
    __syncthreads();
    const float* fb = features + (size_t)b * C_FEAT * HF * WF;
    for (int it = 0; it < 49; it++) {
        int e = it * 256 + tid;
        int c = e / 49;
        int r = e - c * 49;
        int py = r / 7, px = r - py * 7;
        const float* fc = fb + (size_t)c * (HF * WF);
        float acc = 0.0f;
#pragma unroll
        for (int sy = 0; sy < 2; sy++) {
            int i = py * 2 + sy;
            int y0 = sy0[i]; float fy = sly[i];
            const float* rowp = fc + y0 * WF;
#pragma unroll
            for (int sx = 0; sx < 2; sx++) {
                int j = px * 2 + sx;
                int x0 = sx0[j]; float fx = slx[j];
                float v00 = __ldg(rowp + x0);
                float v01 = __ldg(rowp + x0 + 1);
                float v10 = __ldg(rowp + WF + x0);
                float v11 = __ldg(rowp + WF + x0 + 1);
                float top = v00 + (v01 - v00) * fx;
                float bot = v10 + (v11 - v10) * fx;
                acc += top + (bot - top) * fy;
            }
        }
        g_ahi[(size_t)n * DIN + e] = __float2bfloat16_rn(acc * 0.25f);
    }
}

// ---------------- transpose weights to bf16: out[n][k] = bf16(in[k][n]) ----------------
__global__ void k_splitT(const float* __restrict__ in,
                         __nv_bfloat16* __restrict__ oh, int K) {
    __shared__ float t[32][33];
    int nb = blockIdx.x * 32, kb = blockIdx.y * 32;
    int tx = threadIdx.x, ty = threadIdx.y;
#pragma unroll
    for (int r = 0; r < 4; r++)
        t[ty + r * 8][tx] = in[(size_t)(kb + ty + r * 8) * HID + nb + tx];
    __syncthreads();
#pragma unroll
    for (int r = 0; r < 4; r++) {
        int n = nb + ty + r * 8;
        oh[(size_t)n * K + kb + tx] = __float2bfloat16_rn(t[tx][ty + r * 8]);
    }
}

// ---------------- HMMA bf16 GEMM + bias + ReLU ----------------
// C = relu(A @ B^T + bias); A[M][K], B[N][K] bf16.
// CTA 128(M) x 64(N), 4 warps (2x2), warp tile 64x32, BK=32,
// 3-stage cp.async pipeline, ONE __syncthreads per K-step.
// grid = (16, 8) -> 128 CTAs (one wave on 148 SMs).
#define ROWPAD 40                     // bf16 per smem row (80 B, conflict-free ldmatrix)
#define TILE_AB (128 * ROWPAD * 2)    // 10240 B (A)
#define TILE_BB (64 * ROWPAD * 2)     // 5120 B  (B)
#define OFF_BH  TILE_AB
#define STAGE_B (TILE_AB + TILE_BB)   // 15360 B
#define NSTAGES 3
__global__ __launch_bounds__(128, 1) void k_gemm_mma(
    const __nv_bfloat16* __restrict__ Ah,
    const __nv_bfloat16* __restrict__ Bh,
    const float* __restrict__ bias,
    float* __restrict__ Cf, __nv_bfloat16* __restrict__ Ch,
    int K)
{
    extern __shared__ char sm[];
    uint32_t sbase = smem_u32(sm);
    int tid = threadIdx.x, wid = tid >> 5, lane = tid & 31;
    int wm = wid >> 1, wn = wid & 1;              // 2 x 2 warp grid
    int m0 = blockIdx.y << 7, n0 = blockIdx.x << 6;

    float acc[4][4][4];
#pragma unroll
    for (int i = 0; i < 4; i++)
#pragma unroll
        for (int j = 0; j < 4; j++)
#pragma unroll
            for (int q = 0; q < 4; q++) acc[i][j][q] = 0.0f;

    int nsteps = K >> 5;

    // per stage (128 threads): A = 512 16B-chunks (4/thread); B = 256 (2/thread)
#define LOAD_STAGE(st, k0)                                                  \
    {                                                                       \
        uint32_t sb = sbase + (uint32_t)(st) * STAGE_B;                     \
        _Pragma("unroll")                                                   \
        for (int i = 0; i < 4; i++) {                                       \
            int c   = tid + (i << 7);                                       \
            int row = c >> 2, cc = c & 3;                                   \
            uint32_t so = (uint32_t)(row * (ROWPAD * 2) + cc * 16);         \
            size_t goA = (size_t)(m0 + row) * K + (k0) + cc * 8;            \
            cp16(sb + so, Ah + goA);                                        \
        }                                                                   \
        _Pragma("unroll")                                                   \
        for (int i = 0; i < 2; i++) {                                       \
            int c   = tid + (i << 7);                                       \
            int row = c >> 2, cc = c & 3;                                   \
            uint32_t so = (uint32_t)(row * (ROWPAD * 2) + cc * 16);         \
            size_t goB = (size_t)(n0 + row) * K + (k0) + cc * 8;            \
            cp16(sb + OFF_BH + so, Bh + goB);                               \
        }                                                                   \
        asm volatile("cp.async.commit_group;" ::: "memory");                \
    }

    LOAD_STAGE(0, 0)
    if (nsteps > 1) LOAD_STAGE(1, 32)
    else            asm volatile("cp.async.commit_group;" ::: "memory");

    int buf = 0;
    for (int s = 0; s < nsteps; s++) {
        if (s + 1 < nsteps) {
            asm volatile("cp.async.wait_group 1;" ::: "memory");
        } else {
            asm volatile("cp.async.wait_group 0;" ::: "memory");
        }
        __syncthreads();   // stage s visible; all warps past compute s-1 (guards buf (s+2)%3)

        if (s + 2 < nsteps) {
            int nb = buf + 2; if (nb >= NSTAGES) nb -= NSTAGES;
            LOAD_STAGE(nb, (s + 2) << 5)
        }

        uint32_t sb = sbase + (uint32_t)buf * STAGE_B;
#pragma unroll
        for (int kc = 0; kc < 2; kc++) {
            uint32_t ah[4][4], bh[4][2];
            int arow = wm * 64 + (lane & 7) + ((lane >> 3) & 1) * 8;
            int acol = kc * 16 + ((lane >> 4) & 1) * 8;
#pragma unroll
            for (int mi = 0; mi < 4; mi++) {
                uint32_t ad = sb + (uint32_t)((arow + mi * 16) * (ROWPAD * 2) + acol * 2);
                ldsm4(ah[mi], ad);
            }
            int brow = wn * 32 + (lane & 7);
            int bcol = kc * 16 + ((lane >> 3) & 1) * 8;
#pragma unroll
            for (int ni = 0; ni < 4; ni++) {
                uint32_t bd = sb + OFF_BH + (uint32_t)((brow + ni * 8) * (ROWPAD * 2) + bcol * 2);
                ldsm2(bh[ni], bd);
            }
#pragma unroll
            for (int mi = 0; mi < 4; mi++)
#pragma unroll
                for (int ni = 0; ni < 4; ni++)
                    mma_bf16(acc[mi][ni], ah[mi], bh[ni]);
        }
        if (++buf >= NSTAGES) buf = 0;
    }

    // epilogue: c0,c1 -> row r, cols 2c,2c+1 ; c2,c3 -> row r+8
    int r = lane >> 2, cp = (lane & 3) * 2;
#pragma unroll
    for (int mi = 0; mi < 4; mi++) {
        int mA = m0 + wm * 64 + mi * 16 + r;
        int mB = mA + 8;
#pragma unroll
        for (int ni = 0; ni < 4; ni++) {
            int n = n0 + wn * 32 + ni * 8 + cp;
            float b0v = __ldg(bias + n), b1v = __ldg(bias + n + 1);
            float* a = acc[mi][ni];
            float v00 = fmaxf(a[0] + b0v, 0.f), v01 = fmaxf(a[1] + b1v, 0.f);
            float v10 = fmaxf(a[2] + b0v, 0.f), v11 = fmaxf(a[3] + b1v, 0.f);
            if (Cf) {
                *(float2*)(Cf + (size_t)mA * 1024 + n) = make_float2(v00, v01);
                *(float2*)(Cf + (size_t)mB * 1024 + n) = make_float2(v10, v11);
            } else {
                *(ushort2*)(Ch + (size_t)mA * 1024 + n) =
                    make_ushort2(__bfloat16_as_ushort(__float2bfloat16_rn(v00)),
                                 __bfloat16_as_ushort(__float2bfloat16_rn(v01)));
                *(ushort2*)(Ch + (size_t)mB * 1024 + n) =
                    make_ushort2(__bfloat16_as_ushort(__float2bfloat16_rn(v10)),
                                 __bfloat16_as_ushort(__float2bfloat16_rn(v11)));
            }
        }
    }
}

// ---------------- heads ----------------
__global__ __launch_bounds__(128) void k_heads(const float* __restrict__ wc,
                                               const float* __restrict__ bc,
                                               const float* __restrict__ wr,
                                               const float* __restrict__ br) {
    int n = blockIdx.x, tid = threadIdx.x;
    float acc[14];
#pragma unroll
    for (int o = 0; o < 14; o++) acc[o] = 0.0f;
    const float* xr = g_x2 + (size_t)n * HID;
    for (int k = tid; k < HID; k += 128) {
        float xv = xr[k];
        acc[0] = fmaf(xv, wc[k * 2 + 0], acc[0]);
        acc[1] = fmaf(xv, wc[k * 2 + 1], acc[1]);
#pragma unroll
        for (int j = 0; j < 12; j++)
            acc[2 + j] = fmaf(xv, wr[k * 12 + j], acc[2 + j]);
    }
    __shared__ float sh[128];
    for (int o = 0; o < 14; o++) {
        sh[tid] = acc[o]; __syncthreads();
        for (int s = 64; s > 0; s >>= 1) {
            if (tid < s) sh[tid] += sh[tid + s];
            __syncthreads();
        }
        if (tid == 0) {
            float v = sh[0] + (o < 2 ? bc[o] : br[o - 2]);
            if (o < 2) g_logits[n * 2 + o] = v;
            else       g_reg[n * 12 + (o - 2)] = v;
        }
        __syncthreads();
    }
}

// ---------------- losses ----------------
__global__ __launch_bounds__(1024) void k_loss(float* __restrict__ out) {
    int tid = threadIdx.x;
    const float BETA = 1.0f / 9.0f;
    float l0 = g_logits[tid * 2 + 0], l1 = g_logits[tid * 2 + 1];
    int lab = g_labels[tid];
    float mx  = fmaxf(l0, l1);
    float lse = mx + logf(expf(l0 - mx) + expf(l1 - mx));
    float ce  = lse - g_logits[tid * 2 + lab];
    float rl = 0.0f;
    if (lab > 0) {
        const float* pr = g_reg + tid * 12 + lab * 6;
        const float* tg = g_targets + tid * 6;
#pragma unroll
        for (int j = 0; j < 6; j++) {
            float d = fabsf(pr[j] - tg[j]);
            rl += (d < BETA) ? (0.5f * d * d / BETA) : (d - 0.5f * BETA);
        }
    }
    __shared__ float sce[1024];
    __shared__ float srl[1024];
    sce[tid] = ce; srl[tid] = rl;
    __syncthreads();
    for (int s = 512; s > 0; s >>= 1) {
        if (tid < s) { sce[tid] += sce[tid + s]; srl[tid] += srl[tid + s]; }
        __syncthreads();
    }
    if (tid == 0) {
        out[0] = sce[0] / (float)NSAMP;
        out[1] = srl[0] / (float)NSAMP;
    }
}

// ---------------- launch ----------------
extern "C" void kernel_launch(void* const* d_in, const int* in_sizes, int n_in,
                              void* d_out, int out_size) {
    const float* features    = (const float*)d_in[0];
    const float* proposals   = (const float*)d_in[1];
    const float* gt_boxes    = (const float*)d_in[2];
    const int*   gt_labels   = (const int*)  d_in[3];
    const float* gt_ellipses = (const float*)d_in[4];
    const float* w1 = (const float*)d_in[5];
    const float* b1 = (const float*)d_in[6];
    const float* w2 = (const float*)d_in[7];
    const float* b2 = (const float*)d_in[8];
    const float* wc = (const float*)d_in[9];
    const float* bc = (const float*)d_in[10];
    const float* wr = (const float*)d_in[11];
    const float* br = (const float*)d_in[12];
    float* out = (float*)d_out;

    __nv_bfloat16 *pah, *pw1h, *px1h, *pw2h;
    float *px2;
    cudaGetSymbolAddress((void**)&pah,  g_ahi);
    cudaGetSymbolAddress((void**)&pw1h, g_w1th);
    cudaGetSymbolAddress((void**)&px1h, g_x1h);
    cudaGetSymbolAddress((void**)&pw2h, g_w2th);
    cudaGetSymbolAddress((void**)&px2,  g_x2);

    const int dyn_bytes = NSTAGES * STAGE_B;   // 46080
    cudaFuncSetAttribute(k_gemm_mma, cudaFuncAttributeMaxDynamicSharedMemorySize, dyn_bytes);

    k_prep<<<dim3(8, 2), 256>>>(proposals, gt_boxes, gt_labels);
    k_sample<<<2, 1024>>>(gt_ellipses);
    k_roi<<<NSAMP, 256>>>(features);
    k_splitT<<<dim3(32, 392), dim3(32, 8)>>>(w1, pw1h, DIN);
    k_splitT<<<dim3(32, 32),  dim3(32, 8)>>>(w2, pw2h, HID);
    k_gemm_mma<<<dim3(16, 8), 128, dyn_bytes>>>(pah,  pw1h, b1, nullptr, px1h, DIN);
    k_gemm_mma<<<dim3(16, 8), 128, dyn_bytes>>>(px1h, pw2h, b2, px2, nullptr, HID);
    k_heads<<<NSAMP, 128>>>(wc, bc, wr, br);
    k_loss<<<1, 1024>>>(out);
}